// round 12
// baseline (speedup 1.0000x reference)
#include <cuda_runtime.h>
#include <cstdint>

// ---------------- problem constants ----------------
#define NANCH   9216            // 1024*9
#define NWORDS  144             // 9216/64
#define IOU_THR 0.7f
#define TOPK    300

typedef unsigned long long u64;

// ---------------- scratch (static __device__, allocation-free) ----------------
__device__ float  g_feat[512 * 1024];          // backbone features      (2 MB)
__device__ float  g_hid [512 * 1024];          // rpn hidden             (2 MB)
__device__ float  g_part[8 * 512 * 1024];      // split-K partials      (16 MB)
__device__ float  g_head[45 * 1024];           // rows 0..8 cls ch9..17, 9..44 box
__device__ float  g_wh[45 * 512];              // staged head weights
__device__ float  g_bh[45];                    // staged head bias
__device__ float4 g_prop[NANCH];
__device__ u64    g_keys[NANCH];               // 9 sorted runs of 1024
__device__ float4 g_boxes[NANCH];
__device__ u64    g_mask[(size_t)NANCH * NWORDS]; // 10.6 MB

// ---------------- packed f32x2 helpers ----------------
__device__ __forceinline__ void ffma2(u64& d, u64 a, u64 b)
{
    asm("fma.rn.f32x2 %0, %1, %2, %0;" : "+l"(d) : "l"(a), "l"(b));
}
__device__ __forceinline__ u64 pack2(float lo, float hi)
{
    u64 r;
    asm("mov.b64 %0, {%1, %2};" : "=l"(r) : "f"(lo), "f"(hi));
    return r;
}
__device__ __forceinline__ float2 unpack2(u64 v)
{
    float2 r;
    asm("mov.b64 {%0, %1}, %2;" : "=f"(r.x), "=f"(r.y) : "l"(v));
    return r;
}

// ---------------- backbone GEMM, 256 threads, 8x8 micro (proven) ----------------
__global__ void __launch_bounds__(256, 2)
gemm128bb_k(const float* __restrict__ A, const float* __restrict__ img,
            float* __restrict__ P, int ksplit)
{
    __shared__ float As[2][8][132];
    __shared__ float Bs[2][8][128];

    const int bn = blockIdx.x * 128;
    const int bm = blockIdx.y * 128;
    const int kbase = blockIdx.z * ksplit;
    const int tid = threadIdx.x;
    const int tx = tid & 15, ty = tid >> 4;
    const int alm = tid >> 1, alk = (tid & 1) * 4;     // A loader
    const int bkq = (tid >> 7) * 4;                    // B loader: k quad base
    const int bpp = tid & 127;                         // B loader: column

    const float* Aptr = A + (size_t)(bm + alm) * 768 + kbase + alk;
    const int p = bn + bpp, py = p >> 5, px = p & 31;

    u64 acc[8][4];
#pragma unroll
    for (int i = 0; i < 8; i++)
#pragma unroll
        for (int j = 0; j < 4; j++) acc[i][j] = 0ull;

    float4 av = *(const float4*)Aptr;
    int k = kbase + bkq;
    int ci = k >> 8, r = k & 255, ky = r >> 4, kx = r & 15;
    float4 bv = *(const float4*)(img + ci * 262144 + (py * 16 + ky) * 512 + px * 16 + kx);

    As[0][alk + 0][alm] = av.x; As[0][alk + 1][alm] = av.y;
    As[0][alk + 2][alm] = av.z; As[0][alk + 3][alm] = av.w;
    Bs[0][bkq + 0][bpp] = bv.x; Bs[0][bkq + 1][bpp] = bv.y;
    Bs[0][bkq + 2][bpp] = bv.z; Bs[0][bkq + 3][bpp] = bv.w;
    __syncthreads();

    int buf = 0;
    for (int k0 = 0; k0 < ksplit; k0 += 8) {
        bool more = (k0 + 8 < ksplit);
        if (more) {
            av = *(const float4*)(Aptr + k0 + 8);
            k = kbase + k0 + 8 + bkq;
            ci = k >> 8; r = k & 255; ky = r >> 4; kx = r & 15;
            bv = *(const float4*)(img + ci * 262144 + (py * 16 + ky) * 512 + px * 16 + kx);
        }
#pragma unroll
        for (int kk = 0; kk < 8; kk++) {
            float4 a0 = *(const float4*)&As[buf][kk][ty * 4];
            float4 a1 = *(const float4*)&As[buf][kk][ty * 4 + 64];
            const u64* Bk = (const u64*)&Bs[buf][kk][0];
            u64 bb0 = Bk[tx * 2],      bb1 = Bk[tx * 2 + 1];
            u64 bb2 = Bk[tx * 2 + 32], bb3 = Bk[tx * 2 + 33];
            float a[8] = {a0.x, a0.y, a0.z, a0.w, a1.x, a1.y, a1.z, a1.w};
#pragma unroll
            for (int i = 0; i < 8; i++) {
                u64 ad = pack2(a[i], a[i]);
                ffma2(acc[i][0], ad, bb0);
                ffma2(acc[i][1], ad, bb1);
                ffma2(acc[i][2], ad, bb2);
                ffma2(acc[i][3], ad, bb3);
            }
        }
        if (more) {
            int nb = buf ^ 1;
            As[nb][alk + 0][alm] = av.x; As[nb][alk + 1][alm] = av.y;
            As[nb][alk + 2][alm] = av.z; As[nb][alk + 3][alm] = av.w;
            Bs[nb][bkq + 0][bpp] = bv.x; Bs[nb][bkq + 1][bpp] = bv.y;
            Bs[nb][bkq + 2][bpp] = bv.z; Bs[nb][bkq + 3][bpp] = bv.w;
        }
        __syncthreads();
        buf ^= 1;
    }

    float* Pp = P + (size_t)blockIdx.z * 512 * 1024;
#pragma unroll
    for (int ih = 0; ih < 2; ih++)
#pragma unroll
        for (int r2 = 0; r2 < 4; r2++) {
            int i = ih * 4 + r2;
            int m = bm + ih * 64 + ty * 4 + r2;
            float2 p0 = unpack2(acc[i][0]), p1 = unpack2(acc[i][1]);
            float2 p2 = unpack2(acc[i][2]), p3 = unpack2(acc[i][3]);
            *(float4*)(Pp + (size_t)m * 1024 + bn + tx * 4)      = make_float4(p0.x, p0.y, p1.x, p1.y);
            *(float4*)(Pp + (size_t)m * 1024 + bn + tx * 4 + 64) = make_float4(p2.x, p2.y, p3.x, p3.y);
        }
}

// ---------------- rpn GEMM, 512 threads, 4x8 micro, im2col fused ----------------
// B[k][p] = feat[ci][py+dy-1][px+dx-1]; loader: float2 over p per thread.
__device__ __forceinline__ float2 load_feat_pair(int k, int p)
{
    int ci = k / 9, r = k - ci * 9, dy = r / 3, dx = r - dy * 3;
    int py = p >> 5, px = p & 31;                      // px even
    int y = py + dy - 1;
    int x0 = px + dx - 1;                              // -1..31
    float2 v = make_float2(0.f, 0.f);
    if ((unsigned)y < 32u) {
        const float* frow = g_feat + ci * 1024 + y * 32 + x0;
        v.x = (x0 >= 0)     ? frow[0] : 0.f;
        v.y = (x0 + 1 <= 31) ? frow[1] : 0.f;
    }
    return v;
}

__global__ void __launch_bounds__(512, 2)
gemm128rpn_k(const float* __restrict__ A, float* __restrict__ P, int ksplit)
{
    __shared__ float As[2][8][132];
    __shared__ float Bs[2][8][128];

    const int bn = blockIdx.x * 128;
    const int bm = blockIdx.y * 128;
    const int kbase = blockIdx.z * ksplit;
    const int tid = threadIdx.x;
    const int tx = tid & 15, ty = tid >> 4;            // ty 0..31: 4-row groups
    const int alm = tid >> 2, alk = (tid & 3) * 2;     // A loader: float2 over k
    const int blk = tid >> 6, bln = (tid & 63) * 2;    // B loader: float2 over p

    const float* Aptr = A + (size_t)(bm + alm) * 4608 + kbase + alk;
    const int bp = bn + bln;

    u64 acc[4][4];
#pragma unroll
    for (int i = 0; i < 4; i++)
#pragma unroll
        for (int j = 0; j < 4; j++) acc[i][j] = 0ull;

    float2 av = *(const float2*)Aptr;
    float2 bv = load_feat_pair(kbase + blk, bp);

    As[0][alk + 0][alm] = av.x; As[0][alk + 1][alm] = av.y;
    Bs[0][blk][bln] = bv.x; Bs[0][blk][bln + 1] = bv.y;
    __syncthreads();

    int buf = 0;
    for (int k0 = 0; k0 < ksplit; k0 += 8) {
        bool more = (k0 + 8 < ksplit);
        if (more) {
            av = *(const float2*)(Aptr + k0 + 8);
            bv = load_feat_pair(kbase + k0 + 8 + blk, bp);
        }
#pragma unroll
        for (int kk = 0; kk < 8; kk++) {
            float4 a0 = *(const float4*)&As[buf][kk][ty * 4];
            const u64* Bk = (const u64*)&Bs[buf][kk][0];
            u64 bb0 = Bk[tx * 2],      bb1 = Bk[tx * 2 + 1];
            u64 bb2 = Bk[tx * 2 + 32], bb3 = Bk[tx * 2 + 33];
            float a[4] = {a0.x, a0.y, a0.z, a0.w};
#pragma unroll
            for (int i = 0; i < 4; i++) {
                u64 ad = pack2(a[i], a[i]);
                ffma2(acc[i][0], ad, bb0);
                ffma2(acc[i][1], ad, bb1);
                ffma2(acc[i][2], ad, bb2);
                ffma2(acc[i][3], ad, bb3);
            }
        }
        if (more) {
            int nb = buf ^ 1;
            As[nb][alk + 0][alm] = av.x; As[nb][alk + 1][alm] = av.y;
            Bs[nb][blk][bln] = bv.x; Bs[nb][blk][bln + 1] = bv.y;
        }
        __syncthreads();
        buf ^= 1;
    }

    float* Pp = P + (size_t)blockIdx.z * 512 * 1024;
#pragma unroll
    for (int r2 = 0; r2 < 4; r2++) {
        int m = bm + ty * 4 + r2;
        float2 p0 = unpack2(acc[r2][0]), p1 = unpack2(acc[r2][1]);
        float2 p2 = unpack2(acc[r2][2]), p3 = unpack2(acc[r2][3]);
        *(float4*)(Pp + (size_t)m * 1024 + bn + tx * 4)      = make_float4(p0.x, p0.y, p1.x, p1.y);
        *(float4*)(Pp + (size_t)m * 1024 + bn + tx * 4 + 64) = make_float4(p2.x, p2.y, p3.x, p3.y);
    }
}

// ---------------- deterministic split-K reduce (+bias+relu) ----------------
__global__ void reduce_k(const float* __restrict__ P, float* __restrict__ C,
                         const float* __restrict__ bias, int S, int relu)
{
    int idx = blockIdx.x * blockDim.x + threadIdx.x;   // 131072 threads (float4)
    int m = idx >> 8, n4 = (idx & 255) * 4;
    float4 acc = make_float4(0.f, 0.f, 0.f, 0.f);
    for (int s = 0; s < S; s++) {                      // fixed order
        float4 v = *(const float4*)(P + ((size_t)s * 512 + m) * 1024 + n4);
        acc.x += v.x; acc.y += v.y; acc.z += v.z; acc.w += v.w;
    }
    float bb = bias[m];
    acc.x += bb; acc.y += bb; acc.z += bb; acc.w += bb;
    if (relu) {
        acc.x = fmaxf(acc.x, 0.f); acc.y = fmaxf(acc.y, 0.f);
        acc.z = fmaxf(acc.z, 0.f); acc.w = fmaxf(acc.w, 0.f);
    }
    *(float4*)(C + (size_t)m * 1024 + n4) = acc;
}

// ---------------- stage head weights into one contiguous matrix ----------------
__global__ void copy_wh_k(const float* __restrict__ wc, const float* __restrict__ bc,
                          const float* __restrict__ wb, const float* __restrict__ bb2)
{
    int i = blockIdx.x * blockDim.x + threadIdx.x;     // 23040 threads
    if (i < 9 * 512)       g_wh[i] = wc[9 * 512 + i];          // cls ch 9..17
    else if (i < 45 * 512) g_wh[i] = wb[i - 9 * 512];          // box ch 0..35
    if (i < 9)             g_bh[i] = bc[9 + i];
    else if (i < 45)       g_bh[i] = bb2[i - 9];
}

// ---------------- small GEMM for heads: C[45][1024] = wh x hid ----------------
__global__ void gemm_k(const float* __restrict__ A, const float* __restrict__ B,
                       float* __restrict__ C, int M, int K,
                       const float* __restrict__ bias)
{
    __shared__ float As[16][68];
    __shared__ float Bs[16][64];

    const int bn  = blockIdx.x * 64;
    const int tid = threadIdx.x;
    const int tx  = tid & 15, ty = tid >> 4;
    const int lm  = tid >> 2, lkq = (tid & 3) * 4;
    const int lkb = tid >> 4, ln4 = (tid & 15) * 4;

    float acc[4][4] = {};

    float4 av = make_float4(0.f, 0.f, 0.f, 0.f);
    if (lm < M) av = *(const float4*)(A + (size_t)lm * K + lkq);
    float4 bv = *(const float4*)(B + (size_t)lkb * 1024 + bn + ln4);

    for (int k0 = 0; k0 < K; k0 += 16) {
        As[lkq + 0][lm] = av.x; As[lkq + 1][lm] = av.y;
        As[lkq + 2][lm] = av.z; As[lkq + 3][lm] = av.w;
        *(float4*)&Bs[lkb][ln4] = bv;
        __syncthreads();

        int kn = k0 + 16;
        if (kn < K) {
            av = make_float4(0.f, 0.f, 0.f, 0.f);
            if (lm < M) av = *(const float4*)(A + (size_t)lm * K + kn + lkq);
            bv = *(const float4*)(B + (size_t)(kn + lkb) * 1024 + bn + ln4);
        }

#pragma unroll
        for (int k = 0; k < 16; k++) {
            float4 a = *(const float4*)&As[k][ty * 4];
            float4 b = *(const float4*)&Bs[k][tx * 4];
            acc[0][0] += a.x * b.x; acc[0][1] += a.x * b.y; acc[0][2] += a.x * b.z; acc[0][3] += a.x * b.w;
            acc[1][0] += a.y * b.x; acc[1][1] += a.y * b.y; acc[1][2] += a.y * b.z; acc[1][3] += a.y * b.w;
            acc[2][0] += a.z * b.x; acc[2][1] += a.z * b.y; acc[2][2] += a.z * b.z; acc[2][3] += a.z * b.w;
            acc[3][0] += a.w * b.x; acc[3][1] += a.w * b.y; acc[3][2] += a.w * b.z; acc[3][3] += a.w * b.w;
        }
        __syncthreads();
    }

#pragma unroll
    for (int r = 0; r < 4; r++) {
        int m = ty * 4 + r;
        if (m < M) {
            float bb = bias[m];
            float4 o = make_float4(acc[r][0] + bb, acc[r][1] + bb, acc[r][2] + bb, acc[r][3] + bb);
            *(float4*)(C + (size_t)m * 1024 + bn + tx * 4) = o;
        }
    }
}

// ---------------- fused decode + per-run bitonic sort (9 blocks x 512) ----------------
__global__ void decode_sort_k(const float* __restrict__ anchors)
{
    __shared__ u64 sk[1024];
    int base = blockIdx.x << 10, t = threadIdx.x;      // 512 threads

#pragma unroll
    for (int half = 0; half < 2; half++) {
        int e = t + half * 512;
        int i = base + e;
        int p = i / 9, k = i - p * 9;
        float s  = g_head[k * 1024 + p];
        float d0 = g_head[(9 + k * 4 + 0) * 1024 + p];
        float d1 = g_head[(9 + k * 4 + 1) * 1024 + p];
        float d2 = g_head[(9 + k * 4 + 2) * 1024 + p];
        float d3 = g_head[(9 + k * 4 + 3) * 1024 + p];

        const float* a = anchors + (size_t)i * 4;
        float ax1 = a[0], ay1 = a[1], ax2 = a[2], ay2 = a[3];
        float wa = ax2 - ax1, ha = ay2 - ay1;
        float cxa = ax1 + 0.5f * wa, cya = ay1 + 0.5f * ha;
        float dw = fminf(fmaxf(d2, -4.f), 4.f);
        float dh = fminf(fmaxf(d3, -4.f), 4.f);
        float cx = cxa + d0 * wa, cy = cya + d1 * ha;
        float w  = wa * expf(dw), h = ha * expf(dh);
        float x1 = fmaxf(cx - 0.5f * w, 0.f);
        float y1 = fmaxf(cy - 0.5f * h, 0.f);
        float x2 = fminf(cx + 0.5f * w, 511.f);
        float y2 = fminf(cy + 0.5f * h, 511.f);
        g_prop[i] = make_float4(x1, y1, x2, y2);

        unsigned b   = __float_as_uint(s);
        unsigned asc = (b & 0x80000000u) ? ~b : (b | 0x80000000u);
        unsigned dsc = ~asc;
        sk[e] = ((u64)dsc << 32) | (unsigned)i;
    }
    __syncthreads();

    for (int k = 2; k <= 1024; k <<= 1) {
        for (int j = k >> 1; j > 0; j >>= 1) {
            for (int e = t; e < 1024; e += 512) {
                int ixj = e ^ j;
                if (ixj > e) {
                    u64 x = sk[e], y = sk[ixj];
                    bool up = ((e & k) == 0);
                    if (up ? (x > y) : (x < y)) { sk[e] = y; sk[ixj] = x; }
                }
            }
            __syncthreads();
        }
    }
    g_keys[base + t]       = sk[t];
    g_keys[base + t + 512] = sk[t + 512];
}

// ---------------- 9-way rank-merge, fused gather (writes sorted boxes) ----------------
__global__ void merge9_k(const u64* __restrict__ src)
{
    int i = blockIdx.x * blockDim.x + threadIdx.x;     // 9216 threads
    u64 v = src[i];
    int rank = 0;
#pragma unroll
    for (int run = 0; run < 9; run++) {
        const u64* base = src + (run << 10);
        int pos = 0;
#pragma unroll
        for (int w = 512; w >= 1; w >>= 1)
            if (base[pos + w - 1] < v) pos += w;
        if (base[pos] < v) pos++;
        rank += pos;
    }
    g_boxes[rank] = g_prop[(int)(v & 0xFFFFFFFFull)];
}

// ---------------- NMS bitmask (upper triangle only) ----------------
__global__ void nms_mask_k()                           // grid (144, 36), 256 threads
{
    __shared__ float4 cb[64];
    int bx = blockIdx.x;
    int t = threadIdx.x;
    int i = blockIdx.y * 256 + t;
    if (t < 64) cb[t] = g_boxes[bx * 64 + t];
    __syncthreads();

    if (bx < (i >> 6)) return;

    float4 b  = g_boxes[i];
    float  ai = (b.z - b.x) * (b.w - b.y);
    u64 m = 0ull;
#pragma unroll 4
    for (int jj = 0; jj < 64; jj++) {
        int j = bx * 64 + jj;
        if (j > i) {
            float4 c  = cb[jj];
            float  aj = (c.z - c.x) * (c.w - c.y);
            float iw = fmaxf(fminf(b.z, c.z) - fmaxf(b.x, c.x), 0.f);
            float ih = fmaxf(fminf(b.w, c.w) - fmaxf(b.y, c.y), 0.f);
            float inter = iw * ih;
            float iou = inter / (ai + aj - inter + 1e-9f);
            if (iou > IOU_THR) m |= (1ull << jj);
        }
    }
    g_mask[(size_t)i * NWORDS + bx] = m;
}

// ---------------- chunked greedy NMS reduce (exact serial semantics) ----------------
__global__ void nms_reduce_k(float* __restrict__ out)
{
    __shared__ u64 remv[NWORDS];
    __shared__ u64 keepw[NWORDS];
    __shared__ u64 diag[2][64];
    __shared__ int chunkj[64];
    __shared__ int sel[TOPK];
    __shared__ int s_cnt, s_ccnt, s_done;

    int t = threadIdx.x;                               // 192 threads
    if (t < NWORDS) { remv[t] = 0ull; keepw[t] = 0ull; }
    if (t == 0) { s_cnt = 0; s_done = 0; }
    if (t < 64) diag[0][t] = g_mask[(size_t)t * NWORDS + 0];
    __syncthreads();

    for (int c = 0; c < NWORDS; c++) {
        int buf = c & 1;
        if (t == 0) {
            u64 w  = remv[c];
            u64 kw = 0ull;
            int cc = 0;
            int cnt = s_cnt;
            for (int j = 0; j < 64; j++) {
                if (!((w >> j) & 1ull)) {
                    sel[cnt++] = c * 64 + j;
                    kw |= 1ull << j;
                    chunkj[cc++] = j;
                    if (cnt >= TOPK) break;
                    w |= diag[buf][j];
                }
            }
            keepw[c] = kw;
            s_cnt = cnt;
            s_ccnt = cc;
            if (cnt >= TOPK) s_done = 1;
        }
        __syncthreads();
        if (s_done) break;

        if (t >= 64 && t < 128 && c + 1 < NWORDS) {
            int tt = t - 64;
            diag[buf ^ 1][tt] =
                g_mask[(size_t)((c + 1) * 64 + tt) * NWORDS + (c + 1)];
        }

        if (t < NWORDS && t > c) {
            u64 r = remv[t];
            int cc = s_ccnt;
            for (int q = 0; q < cc; q++)
                r |= g_mask[(size_t)(c * 64 + chunkj[q]) * NWORDS + t];
            remv[t] = r;
        }
        __syncthreads();
    }
    __syncthreads();

    if (t == 0 && s_cnt < TOPK) {
        int cnt = s_cnt;
        for (int i = 0; i < NANCH && cnt < TOPK; i++)
            if (!((keepw[i >> 6] >> (i & 63)) & 1ull)) sel[cnt++] = i;
        s_cnt = cnt;
    }
    __syncthreads();

    for (int s = t; s < TOPK; s += blockDim.x) {
        float4 b = g_boxes[sel[s]];
        out[s * 4 + 0] = b.x; out[s * 4 + 1] = b.y;
        out[s * 4 + 2] = b.z; out[s * 4 + 3] = b.w;
    }
}

// ---------------- launch ----------------
extern "C" void kernel_launch(void* const* d_in, const int* in_sizes, int n_in,
                              void* d_out, int out_size)
{
    const float* img     = (const float*)d_in[0];
    const float* anchors = (const float*)d_in[1];
    const float* w_bb    = (const float*)d_in[2];
    const float* b_bb    = (const float*)d_in[3];
    const float* w_rpn   = (const float*)d_in[4];
    const float* b_rpn   = (const float*)d_in[5];
    const float* w_cls   = (const float*)d_in[6];
    const float* b_cls   = (const float*)d_in[7];
    const float* w_box   = (const float*)d_in[8];
    const float* b_box   = (const float*)d_in[9];
    float* out = (float*)d_out;

    float *feat, *hid, *head, *part, *wh, *bh;
    u64 *keys;
    cudaGetSymbolAddress((void**)&feat,  g_feat);
    cudaGetSymbolAddress((void**)&hid,   g_hid);
    cudaGetSymbolAddress((void**)&head,  g_head);
    cudaGetSymbolAddress((void**)&part,  g_part);
    cudaGetSymbolAddress((void**)&wh,    g_wh);
    cudaGetSymbolAddress((void**)&bh,    g_bh);
    cudaGetSymbolAddress((void**)&keys,  g_keys);

    copy_wh_k<<<90, 256>>>(w_cls, b_cls, w_box, b_box);            // #1 (independent)

    // backbone conv, im2col fused: split-K 4 (K=768, ksplit=192)
    gemm128bb_k<<<dim3(8, 4, 4), 256>>>(w_bb, img, part, 192);     // #2
    reduce_k<<<512, 256>>>(part, feat, b_bb, 4, 1);                // #3

    // rpn conv, im2col fused: split-K 8 (K=4608, ksplit=576), 512-thread CTAs
    gemm128rpn_k<<<dim3(8, 4, 8), 512>>>(w_rpn, part, 576);        // #4 <- profiled
    reduce_k<<<512, 256>>>(part, hid, b_rpn, 8, 1);                // #5

    // heads: one 45-row GEMM
    gemm_k<<<16, 256>>>(wh, hid, head, 45, 512, bh);               // #6

    // decode + per-run sort (fused), then 9-way rank-merge writing sorted boxes
    decode_sort_k<<<9, 512>>>(anchors);                            // #7
    merge9_k<<<36, 256>>>(keys);                                   // #8

    // NMS
    nms_mask_k<<<dim3(NWORDS, 36), 256>>>();                       // #9
    nms_reduce_k<<<1, 192>>>(out);                                 // #10
}

// round 13
// speedup vs baseline: 1.0582x; 1.0582x over previous
#include <cuda_runtime.h>
#include <cstdint>

// ---------------- problem constants ----------------
#define NANCH   9216            // 1024*9
#define NWORDS  144             // 9216/64
#define IOU_THR 0.7f
#define TOPK    300

typedef unsigned long long u64;

// ---------------- scratch (static __device__, allocation-free) ----------------
__device__ float  g_feat[512 * 1024];          // backbone features      (2 MB)
__device__ float  g_hid [512 * 1024];          // rpn hidden             (2 MB)
__device__ float  g_part[8 * 512 * 1024];      // split-K partials      (16 MB)
__device__ float  g_head[45 * 1024];           // rows 0..8 cls ch9..17, 9..44 box
__device__ float  g_wh[45 * 512];              // staged head weights
__device__ float  g_bh[45];                    // staged head bias
__device__ float4 g_prop[NANCH];
__device__ u64    g_keys[NANCH];               // 9 sorted runs of 1024
__device__ float4 g_boxes[NANCH];
__device__ u64    g_mask[(size_t)NANCH * NWORDS]; // 10.6 MB

// ---------------- packed f32x2 helpers ----------------
__device__ __forceinline__ void ffma2(u64& d, u64 a, u64 b)
{
    asm("fma.rn.f32x2 %0, %1, %2, %0;" : "+l"(d) : "l"(a), "l"(b));
}
__device__ __forceinline__ u64 pack2(float lo, float hi)
{
    u64 r;
    asm("mov.b64 %0, {%1, %2};" : "=l"(r) : "f"(lo), "f"(hi));
    return r;
}
__device__ __forceinline__ float2 unpack2(u64 v)
{
    float2 r;
    asm("mov.b64 {%0, %1}, %2;" : "=f"(r.x), "=f"(r.y) : "l"(v));
    return r;
}

// ---------------- backbone GEMM, 256 threads, 8x8 micro, im2col fused ----------------
// B[k][p] = img[ci][py*16+ky][px*16+kx], k=ci*256+ky*16+kx, p=py*32+px.
__global__ void __launch_bounds__(256, 2)
gemm128bb_k(const float* __restrict__ A, const float* __restrict__ img,
            float* __restrict__ P, int ksplit)
{
    __shared__ float As[2][8][132];
    __shared__ float Bs[2][8][128];

    const int bn = blockIdx.x * 128;
    const int bm = blockIdx.y * 128;
    const int kbase = blockIdx.z * ksplit;
    const int tid = threadIdx.x;
    const int tx = tid & 15, ty = tid >> 4;
    const int alm = tid >> 1, alk = (tid & 1) * 4;     // A loader
    const int bkq = (tid >> 7) * 4;                    // B loader: k quad base
    const int bpp = tid & 127;                         // B loader: column

    const float* Aptr = A + (size_t)(bm + alm) * 768 + kbase + alk;
    const int p = bn + bpp, py = p >> 5, px = p & 31;

    u64 acc[8][4];
#pragma unroll
    for (int i = 0; i < 8; i++)
#pragma unroll
        for (int j = 0; j < 4; j++) acc[i][j] = 0ull;

    float4 av = *(const float4*)Aptr;
    int k = kbase + bkq;
    int ci = k >> 8, r = k & 255, ky = r >> 4, kx = r & 15;
    float4 bv = *(const float4*)(img + ci * 262144 + (py * 16 + ky) * 512 + px * 16 + kx);

    As[0][alk + 0][alm] = av.x; As[0][alk + 1][alm] = av.y;
    As[0][alk + 2][alm] = av.z; As[0][alk + 3][alm] = av.w;
    Bs[0][bkq + 0][bpp] = bv.x; Bs[0][bkq + 1][bpp] = bv.y;
    Bs[0][bkq + 2][bpp] = bv.z; Bs[0][bkq + 3][bpp] = bv.w;
    __syncthreads();

    int buf = 0;
    for (int k0 = 0; k0 < ksplit; k0 += 8) {
        bool more = (k0 + 8 < ksplit);
        if (more) {
            av = *(const float4*)(Aptr + k0 + 8);
            k = kbase + k0 + 8 + bkq;
            ci = k >> 8; r = k & 255; ky = r >> 4; kx = r & 15;
            bv = *(const float4*)(img + ci * 262144 + (py * 16 + ky) * 512 + px * 16 + kx);
        }
#pragma unroll
        for (int kk = 0; kk < 8; kk++) {
            float4 a0 = *(const float4*)&As[buf][kk][ty * 4];
            float4 a1 = *(const float4*)&As[buf][kk][ty * 4 + 64];
            const u64* Bk = (const u64*)&Bs[buf][kk][0];
            u64 bb0 = Bk[tx * 2],      bb1 = Bk[tx * 2 + 1];
            u64 bb2 = Bk[tx * 2 + 32], bb3 = Bk[tx * 2 + 33];
            float a[8] = {a0.x, a0.y, a0.z, a0.w, a1.x, a1.y, a1.z, a1.w};
#pragma unroll
            for (int i = 0; i < 8; i++) {
                u64 ad = pack2(a[i], a[i]);
                ffma2(acc[i][0], ad, bb0);
                ffma2(acc[i][1], ad, bb1);
                ffma2(acc[i][2], ad, bb2);
                ffma2(acc[i][3], ad, bb3);
            }
        }
        if (more) {
            int nb = buf ^ 1;
            As[nb][alk + 0][alm] = av.x; As[nb][alk + 1][alm] = av.y;
            As[nb][alk + 2][alm] = av.z; As[nb][alk + 3][alm] = av.w;
            Bs[nb][bkq + 0][bpp] = bv.x; Bs[nb][bkq + 1][bpp] = bv.y;
            Bs[nb][bkq + 2][bpp] = bv.z; Bs[nb][bkq + 3][bpp] = bv.w;
        }
        __syncthreads();
        buf ^= 1;
    }

    float* Pp = P + (size_t)blockIdx.z * 512 * 1024;
#pragma unroll
    for (int ih = 0; ih < 2; ih++)
#pragma unroll
        for (int r2 = 0; r2 < 4; r2++) {
            int i = ih * 4 + r2;
            int m = bm + ih * 64 + ty * 4 + r2;
            float2 p0 = unpack2(acc[i][0]), p1 = unpack2(acc[i][1]);
            float2 p2 = unpack2(acc[i][2]), p3 = unpack2(acc[i][3]);
            *(float4*)(Pp + (size_t)m * 1024 + bn + tx * 4)      = make_float4(p0.x, p0.y, p1.x, p1.y);
            *(float4*)(Pp + (size_t)m * 1024 + bn + tx * 4 + 64) = make_float4(p2.x, p2.y, p3.x, p3.y);
        }
}

// ---------------- rpn GEMM, 256 threads, 8x8 micro, im2col fused (R10 proven) ----------------
__device__ __forceinline__ float4 load_feat_quad(int k, int p)
{
    int ci = k / 9, r = k - ci * 9, dy = r / 3, dx = r - dy * 3;
    int py = p >> 5, px = p & 31;                      // px multiple of 4
    int y = py + dy - 1;
    int x0 = px + dx - 1;
    float4 v = make_float4(0.f, 0.f, 0.f, 0.f);
    if ((unsigned)y < 32u) {
        const float* frow = g_feat + ci * 1024 + y * 32 + x0;
        v.x = (x0 >= 0) ? frow[0] : 0.f;
        v.y = frow[1];
        v.z = frow[2];
        v.w = (x0 + 3 <= 31) ? frow[3] : 0.f;
    }
    return v;
}

__global__ void __launch_bounds__(256, 2)
gemm128rpn_k(const float* __restrict__ A, float* __restrict__ P, int ksplit)
{
    __shared__ float As[2][8][132];
    __shared__ float Bs[2][8][128];

    const int bn = blockIdx.x * 128;
    const int bm = blockIdx.y * 128;
    const int kbase = blockIdx.z * ksplit;
    const int tid = threadIdx.x;
    const int tx = tid & 15, ty = tid >> 4;
    const int alm = tid >> 1, alk = (tid & 1) * 4;
    const int blk = tid >> 5, bln = (tid & 31) * 4;

    const float* Aptr = A + (size_t)(bm + alm) * 4608 + kbase + alk;
    const int bp = bn + bln;

    u64 acc[8][4];
#pragma unroll
    for (int i = 0; i < 8; i++)
#pragma unroll
        for (int j = 0; j < 4; j++) acc[i][j] = 0ull;

    float4 av = *(const float4*)Aptr;
    float4 bv = load_feat_quad(kbase + blk, bp);

    As[0][alk + 0][alm] = av.x; As[0][alk + 1][alm] = av.y;
    As[0][alk + 2][alm] = av.z; As[0][alk + 3][alm] = av.w;
    *(float4*)&Bs[0][blk][bln] = bv;
    __syncthreads();

    int buf = 0;
    for (int k0 = 0; k0 < ksplit; k0 += 8) {
        bool more = (k0 + 8 < ksplit);
        if (more) {
            av = *(const float4*)(Aptr + k0 + 8);
            bv = load_feat_quad(kbase + k0 + 8 + blk, bp);
        }
#pragma unroll
        for (int kk = 0; kk < 8; kk++) {
            float4 a0 = *(const float4*)&As[buf][kk][ty * 4];
            float4 a1 = *(const float4*)&As[buf][kk][ty * 4 + 64];
            const u64* Bk = (const u64*)&Bs[buf][kk][0];
            u64 bb0 = Bk[tx * 2],      bb1 = Bk[tx * 2 + 1];
            u64 bb2 = Bk[tx * 2 + 32], bb3 = Bk[tx * 2 + 33];
            float a[8] = {a0.x, a0.y, a0.z, a0.w, a1.x, a1.y, a1.z, a1.w};
#pragma unroll
            for (int i = 0; i < 8; i++) {
                u64 ad = pack2(a[i], a[i]);
                ffma2(acc[i][0], ad, bb0);
                ffma2(acc[i][1], ad, bb1);
                ffma2(acc[i][2], ad, bb2);
                ffma2(acc[i][3], ad, bb3);
            }
        }
        if (more) {
            int nb = buf ^ 1;
            As[nb][alk + 0][alm] = av.x; As[nb][alk + 1][alm] = av.y;
            As[nb][alk + 2][alm] = av.z; As[nb][alk + 3][alm] = av.w;
            *(float4*)&Bs[nb][blk][bln] = bv;
        }
        __syncthreads();
        buf ^= 1;
    }

    float* Pp = P + (size_t)blockIdx.z * 512 * 1024;
#pragma unroll
    for (int ih = 0; ih < 2; ih++)
#pragma unroll
        for (int r2 = 0; r2 < 4; r2++) {
            int i = ih * 4 + r2;
            int m = bm + ih * 64 + ty * 4 + r2;
            float2 p0 = unpack2(acc[i][0]), p1 = unpack2(acc[i][1]);
            float2 p2 = unpack2(acc[i][2]), p3 = unpack2(acc[i][3]);
            *(float4*)(Pp + (size_t)m * 1024 + bn + tx * 4)      = make_float4(p0.x, p0.y, p1.x, p1.y);
            *(float4*)(Pp + (size_t)m * 1024 + bn + tx * 4 + 64) = make_float4(p2.x, p2.y, p3.x, p3.y);
        }
}

// ---------------- deterministic split-K reduce (+bias+relu) ----------------
__global__ void reduce_k(const float* __restrict__ P, float* __restrict__ C,
                         const float* __restrict__ bias, int S, int relu)
{
    int idx = blockIdx.x * blockDim.x + threadIdx.x;   // 131072 threads (float4)
    int m = idx >> 8, n4 = (idx & 255) * 4;
    float4 acc = make_float4(0.f, 0.f, 0.f, 0.f);
    for (int s = 0; s < S; s++) {                      // fixed order
        float4 v = *(const float4*)(P + ((size_t)s * 512 + m) * 1024 + n4);
        acc.x += v.x; acc.y += v.y; acc.z += v.z; acc.w += v.w;
    }
    float bb = bias[m];
    acc.x += bb; acc.y += bb; acc.z += bb; acc.w += bb;
    if (relu) {
        acc.x = fmaxf(acc.x, 0.f); acc.y = fmaxf(acc.y, 0.f);
        acc.z = fmaxf(acc.z, 0.f); acc.w = fmaxf(acc.w, 0.f);
    }
    *(float4*)(C + (size_t)m * 1024 + n4) = acc;
}

// ---------------- stage head weights into one contiguous matrix ----------------
__global__ void copy_wh_k(const float* __restrict__ wc, const float* __restrict__ bc,
                          const float* __restrict__ wb, const float* __restrict__ bb2)
{
    int i = blockIdx.x * blockDim.x + threadIdx.x;     // 23040 threads
    if (i < 9 * 512)       g_wh[i] = wc[9 * 512 + i];          // cls ch 9..17
    else if (i < 45 * 512) g_wh[i] = wb[i - 9 * 512];          // box ch 0..35
    if (i < 9)             g_bh[i] = bc[9 + i];
    else if (i < 45)       g_bh[i] = bb2[i - 9];
}

// ---------------- small GEMM for heads: C[45][1024] = wh x hid ----------------
__global__ void gemm_k(const float* __restrict__ A, const float* __restrict__ B,
                       float* __restrict__ C, int M, int K,
                       const float* __restrict__ bias)
{
    __shared__ float As[16][68];
    __shared__ float Bs[16][64];

    const int bn  = blockIdx.x * 64;
    const int tid = threadIdx.x;
    const int tx  = tid & 15, ty = tid >> 4;
    const int lm  = tid >> 2, lkq = (tid & 3) * 4;
    const int lkb = tid >> 4, ln4 = (tid & 15) * 4;

    float acc[4][4] = {};

    float4 av = make_float4(0.f, 0.f, 0.f, 0.f);
    if (lm < M) av = *(const float4*)(A + (size_t)lm * K + lkq);
    float4 bv = *(const float4*)(B + (size_t)lkb * 1024 + bn + ln4);

    for (int k0 = 0; k0 < K; k0 += 16) {
        As[lkq + 0][lm] = av.x; As[lkq + 1][lm] = av.y;
        As[lkq + 2][lm] = av.z; As[lkq + 3][lm] = av.w;
        *(float4*)&Bs[lkb][ln4] = bv;
        __syncthreads();

        int kn = k0 + 16;
        if (kn < K) {
            av = make_float4(0.f, 0.f, 0.f, 0.f);
            if (lm < M) av = *(const float4*)(A + (size_t)lm * K + kn + lkq);
            bv = *(const float4*)(B + (size_t)(kn + lkb) * 1024 + bn + ln4);
        }

#pragma unroll
        for (int k = 0; k < 16; k++) {
            float4 a = *(const float4*)&As[k][ty * 4];
            float4 b = *(const float4*)&Bs[k][tx * 4];
            acc[0][0] += a.x * b.x; acc[0][1] += a.x * b.y; acc[0][2] += a.x * b.z; acc[0][3] += a.x * b.w;
            acc[1][0] += a.y * b.x; acc[1][1] += a.y * b.y; acc[1][2] += a.y * b.z; acc[1][3] += a.y * b.w;
            acc[2][0] += a.z * b.x; acc[2][1] += a.z * b.y; acc[2][2] += a.z * b.z; acc[2][3] += a.z * b.w;
            acc[3][0] += a.w * b.x; acc[3][1] += a.w * b.y; acc[3][2] += a.w * b.z; acc[3][3] += a.w * b.w;
        }
        __syncthreads();
    }

#pragma unroll
    for (int r = 0; r < 4; r++) {
        int m = ty * 4 + r;
        if (m < M) {
            float bb = bias[m];
            float4 o = make_float4(acc[r][0] + bb, acc[r][1] + bb, acc[r][2] + bb, acc[r][3] + bb);
            *(float4*)(C + (size_t)m * 1024 + bn + tx * 4) = o;
        }
    }
}

// ---------------- fused decode + per-run bitonic sort (9 blocks x 512) ----------------
__global__ void decode_sort_k(const float* __restrict__ anchors)
{
    __shared__ u64 sk[1024];
    int base = blockIdx.x << 10, t = threadIdx.x;      // 512 threads

#pragma unroll
    for (int half = 0; half < 2; half++) {
        int e = t + half * 512;
        int i = base + e;
        int p = i / 9, k = i - p * 9;
        float s  = g_head[k * 1024 + p];
        float d0 = g_head[(9 + k * 4 + 0) * 1024 + p];
        float d1 = g_head[(9 + k * 4 + 1) * 1024 + p];
        float d2 = g_head[(9 + k * 4 + 2) * 1024 + p];
        float d3 = g_head[(9 + k * 4 + 3) * 1024 + p];

        const float* a = anchors + (size_t)i * 4;
        float ax1 = a[0], ay1 = a[1], ax2 = a[2], ay2 = a[3];
        float wa = ax2 - ax1, ha = ay2 - ay1;
        float cxa = ax1 + 0.5f * wa, cya = ay1 + 0.5f * ha;
        float dw = fminf(fmaxf(d2, -4.f), 4.f);
        float dh = fminf(fmaxf(d3, -4.f), 4.f);
        float cx = cxa + d0 * wa, cy = cya + d1 * ha;
        float w  = wa * expf(dw), h = ha * expf(dh);
        float x1 = fmaxf(cx - 0.5f * w, 0.f);
        float y1 = fmaxf(cy - 0.5f * h, 0.f);
        float x2 = fminf(cx + 0.5f * w, 511.f);
        float y2 = fminf(cy + 0.5f * h, 511.f);
        g_prop[i] = make_float4(x1, y1, x2, y2);

        unsigned b   = __float_as_uint(s);
        unsigned asc = (b & 0x80000000u) ? ~b : (b | 0x80000000u);
        unsigned dsc = ~asc;
        sk[e] = ((u64)dsc << 32) | (unsigned)i;
    }
    __syncthreads();

    for (int k = 2; k <= 1024; k <<= 1) {
        for (int j = k >> 1; j > 0; j >>= 1) {
            for (int e = t; e < 1024; e += 512) {
                int ixj = e ^ j;
                if (ixj > e) {
                    u64 x = sk[e], y = sk[ixj];
                    bool up = ((e & k) == 0);
                    if (up ? (x > y) : (x < y)) { sk[e] = y; sk[ixj] = x; }
                }
            }
            __syncthreads();
        }
    }
    g_keys[base + t]       = sk[t];
    g_keys[base + t + 512] = sk[t + 512];
}

// ---------------- 9-way rank-merge, fused gather (writes sorted boxes) ----------------
__global__ void merge9_k(const u64* __restrict__ src)
{
    int i = blockIdx.x * blockDim.x + threadIdx.x;     // 9216 threads
    u64 v = src[i];
    int rank = 0;
#pragma unroll
    for (int run = 0; run < 9; run++) {
        const u64* base = src + (run << 10);
        int pos = 0;
#pragma unroll
        for (int w = 512; w >= 1; w >>= 1)
            if (base[pos + w - 1] < v) pos += w;
        if (base[pos] < v) pos++;
        rank += pos;
    }
    g_boxes[rank] = g_prop[(int)(v & 0xFFFFFFFFull)];
}

// ---------------- NMS bitmask (upper triangle only; sub-diagonal blocks exit pre-load) ----------------
__global__ void nms_mask_k()                           // grid (144, 36), 256 threads
{
    __shared__ float4 cb[64];
    int bx = blockIdx.x;
    int by = blockIdx.y;
    if (bx < by * 4) return;                           // whole block below diagonal: uniform exit

    int t = threadIdx.x;
    int i = by * 256 + t;
    if (t < 64) cb[t] = g_boxes[bx * 64 + t];
    __syncthreads();

    if (bx < (i >> 6)) return;                         // per-row: word never read

    float4 b  = g_boxes[i];
    float  ai = (b.z - b.x) * (b.w - b.y);
    u64 m = 0ull;
#pragma unroll 4
    for (int jj = 0; jj < 64; jj++) {
        int j = bx * 64 + jj;
        if (j > i) {
            float4 c  = cb[jj];
            float  aj = (c.z - c.x) * (c.w - c.y);
            float iw = fmaxf(fminf(b.z, c.z) - fmaxf(b.x, c.x), 0.f);
            float ih = fmaxf(fminf(b.w, c.w) - fmaxf(b.y, c.y), 0.f);
            float inter = iw * ih;
            float iou = inter / (ai + aj - inter + 1e-9f);
            if (iou > IOU_THR) m |= (1ull << jj);
        }
    }
    g_mask[(size_t)i * NWORDS + bx] = m;
}

// ---------------- chunked greedy NMS reduce (exact serial semantics) ----------------
__global__ void nms_reduce_k(float* __restrict__ out)
{
    __shared__ u64 remv[NWORDS];
    __shared__ u64 keepw[NWORDS];
    __shared__ u64 diag[2][64];
    __shared__ int chunkj[64];
    __shared__ int sel[TOPK];
    __shared__ int s_cnt, s_ccnt, s_done;

    int t = threadIdx.x;                               // 192 threads
    if (t < NWORDS) { remv[t] = 0ull; keepw[t] = 0ull; }
    if (t == 0) { s_cnt = 0; s_done = 0; }
    if (t < 64) diag[0][t] = g_mask[(size_t)t * NWORDS + 0];
    __syncthreads();

    for (int c = 0; c < NWORDS; c++) {
        int buf = c & 1;
        if (t == 0) {
            u64 w  = remv[c];
            u64 kw = 0ull;
            int cc = 0;
            int cnt = s_cnt;
            for (int j = 0; j < 64; j++) {
                if (!((w >> j) & 1ull)) {
                    sel[cnt++] = c * 64 + j;
                    kw |= 1ull << j;
                    chunkj[cc++] = j;
                    if (cnt >= TOPK) break;
                    w |= diag[buf][j];
                }
            }
            keepw[c] = kw;
            s_cnt = cnt;
            s_ccnt = cc;
            if (cnt >= TOPK) s_done = 1;
        }
        __syncthreads();
        if (s_done) break;

        if (t >= 64 && t < 128 && c + 1 < NWORDS) {
            int tt = t - 64;
            diag[buf ^ 1][tt] =
                g_mask[(size_t)((c + 1) * 64 + tt) * NWORDS + (c + 1)];
        }

        if (t < NWORDS && t > c) {
            u64 r = remv[t];
            int cc = s_ccnt;
            for (int q = 0; q < cc; q++)
                r |= g_mask[(size_t)(c * 64 + chunkj[q]) * NWORDS + t];
            remv[t] = r;
        }
        __syncthreads();
    }
    __syncthreads();

    if (t == 0 && s_cnt < TOPK) {
        int cnt = s_cnt;
        for (int i = 0; i < NANCH && cnt < TOPK; i++)
            if (!((keepw[i >> 6] >> (i & 63)) & 1ull)) sel[cnt++] = i;
        s_cnt = cnt;
    }
    __syncthreads();

    for (int s = t; s < TOPK; s += blockDim.x) {
        float4 b = g_boxes[sel[s]];
        out[s * 4 + 0] = b.x; out[s * 4 + 1] = b.y;
        out[s * 4 + 2] = b.z; out[s * 4 + 3] = b.w;
    }
}

// ---------------- launch ----------------
extern "C" void kernel_launch(void* const* d_in, const int* in_sizes, int n_in,
                              void* d_out, int out_size)
{
    const float* img     = (const float*)d_in[0];
    const float* anchors = (const float*)d_in[1];
    const float* w_bb    = (const float*)d_in[2];
    const float* b_bb    = (const float*)d_in[3];
    const float* w_rpn   = (const float*)d_in[4];
    const float* b_rpn   = (const float*)d_in[5];
    const float* w_cls   = (const float*)d_in[6];
    const float* b_cls   = (const float*)d_in[7];
    const float* w_box   = (const float*)d_in[8];
    const float* b_box   = (const float*)d_in[9];
    float* out = (float*)d_out;

    float *feat, *hid, *head, *part, *wh, *bh;
    u64 *keys;
    cudaGetSymbolAddress((void**)&feat,  g_feat);
    cudaGetSymbolAddress((void**)&hid,   g_hid);
    cudaGetSymbolAddress((void**)&head,  g_head);
    cudaGetSymbolAddress((void**)&part,  g_part);
    cudaGetSymbolAddress((void**)&wh,    g_wh);
    cudaGetSymbolAddress((void**)&bh,    g_bh);
    cudaGetSymbolAddress((void**)&keys,  g_keys);

    copy_wh_k<<<90, 256>>>(w_cls, b_cls, w_box, b_box);            // #1 (independent)

    // backbone conv, im2col fused: split-K 8 (K=768, ksplit=96) -> 256 CTAs
    gemm128bb_k<<<dim3(8, 4, 8), 256>>>(w_bb, img, part, 96);      // #2
    reduce_k<<<512, 256>>>(part, feat, b_bb, 8, 1);                // #3

    // rpn conv, im2col fused: split-K 8 (K=4608, ksplit=576), 256-thread CTAs
    gemm128rpn_k<<<dim3(8, 4, 8), 256>>>(w_rpn, part, 576);        // #4 <- profiled
    reduce_k<<<512, 256>>>(part, hid, b_rpn, 8, 1);                // #5

    // heads: one 45-row GEMM
    gemm_k<<<16, 256>>>(wh, hid, head, 45, 512, bh);               // #6

    // decode + per-run sort (fused), then 9-way rank-merge writing sorted boxes
    decode_sort_k<<<9, 512>>>(anchors);                            // #7
    merge9_k<<<36, 256>>>(keys);                                   // #8

    // NMS
    nms_mask_k<<<dim3(NWORDS, 36), 256>>>();                       // #9
    nms_reduce_k<<<1, 192>>>(out);                                 // #10
}

// round 14
// speedup vs baseline: 1.0908x; 1.0308x over previous
#include <cuda_runtime.h>
#include <cstdint>

// ---------------- problem constants ----------------
#define NANCH   9216            // 1024*9
#define NWORDS  144             // 9216/64
#define IOU_THR 0.7f
#define TOPK    300

typedef unsigned long long u64;

// ---------------- scratch (static __device__, allocation-free) ----------------
__device__ float  g_feat[512 * 1024];          // backbone features      (2 MB)
__device__ float  g_hid [512 * 1024];          // rpn hidden             (2 MB)
__device__ float  g_part[9 * 512 * 1024];      // split-K partials      (19 MB)
__device__ float  g_head[45 * 1024];           // rows 0..8 cls ch9..17, 9..44 box
__device__ float  g_wh[45 * 512];              // staged head weights
__device__ float  g_bh[45];                    // staged head bias
__device__ float4 g_prop[NANCH];
__device__ u64    g_keys[NANCH];               // 9 sorted runs of 1024
__device__ float4 g_boxes[NANCH];
__device__ u64    g_mask[(size_t)NANCH * NWORDS]; // 10.6 MB

// ---------------- packed f32x2 helpers ----------------
__device__ __forceinline__ void ffma2(u64& d, u64 a, u64 b)
{
    asm("fma.rn.f32x2 %0, %1, %2, %0;" : "+l"(d) : "l"(a), "l"(b));
}
__device__ __forceinline__ u64 pack2(float lo, float hi)
{
    u64 r;
    asm("mov.b64 %0, {%1, %2};" : "=l"(r) : "f"(lo), "f"(hi));
    return r;
}
__device__ __forceinline__ float2 unpack2(u64 v)
{
    float2 r;
    asm("mov.b64 {%0, %1}, %2;" : "=f"(r.x), "=f"(r.y) : "l"(v));
    return r;
}

// ---------------- backbone GEMM, 256 threads, 8x8 micro, im2col fused ----------------
// B[k][p] = img[ci][py*16+ky][px*16+kx], k=ci*256+ky*16+kx, p=py*32+px.
// Loader k-fast: thread pairs (2t,2t+1) read 32B contiguous (kx, kx+4 quads).
__global__ void __launch_bounds__(256, 2)
gemm128bb_k(const float* __restrict__ A, const float* __restrict__ img,
            float* __restrict__ P, int ksplit)
{
    __shared__ float As[2][8][132];
    __shared__ float Bs[2][8][128];

    const int bn = blockIdx.x * 128;
    const int bm = blockIdx.y * 128;
    const int kbase = blockIdx.z * ksplit;
    const int tid = threadIdx.x;
    const int tx = tid & 15, ty = tid >> 4;
    const int alm = tid >> 1, alk = (tid & 1) * 4;     // A loader
    const int bkq = (tid & 1) * 4;                     // B loader: k quad (k-fast)
    const int bpp = tid >> 1;                          // B loader: column

    const float* Aptr = A + (size_t)(bm + alm) * 768 + kbase + alk;
    const int p = bn + bpp, py = p >> 5, px = p & 31;

    u64 acc[8][4];
#pragma unroll
    for (int i = 0; i < 8; i++)
#pragma unroll
        for (int j = 0; j < 4; j++) acc[i][j] = 0ull;

    float4 av = *(const float4*)Aptr;
    int k = kbase + bkq;
    int ci = k >> 8, r = k & 255, ky = r >> 4, kx = r & 15;
    float4 bv = *(const float4*)(img + ci * 262144 + (py * 16 + ky) * 512 + px * 16 + kx);

    As[0][alk + 0][alm] = av.x; As[0][alk + 1][alm] = av.y;
    As[0][alk + 2][alm] = av.z; As[0][alk + 3][alm] = av.w;
    Bs[0][bkq + 0][bpp] = bv.x; Bs[0][bkq + 1][bpp] = bv.y;
    Bs[0][bkq + 2][bpp] = bv.z; Bs[0][bkq + 3][bpp] = bv.w;
    __syncthreads();

    int buf = 0;
    for (int k0 = 0; k0 < ksplit; k0 += 8) {
        bool more = (k0 + 8 < ksplit);
        if (more) {
            av = *(const float4*)(Aptr + k0 + 8);
            k = kbase + k0 + 8 + bkq;
            ci = k >> 8; r = k & 255; ky = r >> 4; kx = r & 15;
            bv = *(const float4*)(img + ci * 262144 + (py * 16 + ky) * 512 + px * 16 + kx);
        }
#pragma unroll
        for (int kk = 0; kk < 8; kk++) {
            float4 a0 = *(const float4*)&As[buf][kk][ty * 4];
            float4 a1 = *(const float4*)&As[buf][kk][ty * 4 + 64];
            const u64* Bk = (const u64*)&Bs[buf][kk][0];
            u64 bb0 = Bk[tx * 2],      bb1 = Bk[tx * 2 + 1];
            u64 bb2 = Bk[tx * 2 + 32], bb3 = Bk[tx * 2 + 33];
            float a[8] = {a0.x, a0.y, a0.z, a0.w, a1.x, a1.y, a1.z, a1.w};
#pragma unroll
            for (int i = 0; i < 8; i++) {
                u64 ad = pack2(a[i], a[i]);
                ffma2(acc[i][0], ad, bb0);
                ffma2(acc[i][1], ad, bb1);
                ffma2(acc[i][2], ad, bb2);
                ffma2(acc[i][3], ad, bb3);
            }
        }
        if (more) {
            int nb = buf ^ 1;
            As[nb][alk + 0][alm] = av.x; As[nb][alk + 1][alm] = av.y;
            As[nb][alk + 2][alm] = av.z; As[nb][alk + 3][alm] = av.w;
            Bs[nb][bkq + 0][bpp] = bv.x; Bs[nb][bkq + 1][bpp] = bv.y;
            Bs[nb][bkq + 2][bpp] = bv.z; Bs[nb][bkq + 3][bpp] = bv.w;
        }
        __syncthreads();
        buf ^= 1;
    }

    float* Pp = P + (size_t)blockIdx.z * 512 * 1024;
#pragma unroll
    for (int ih = 0; ih < 2; ih++)
#pragma unroll
        for (int r2 = 0; r2 < 4; r2++) {
            int i = ih * 4 + r2;
            int m = bm + ih * 64 + ty * 4 + r2;
            float2 p0 = unpack2(acc[i][0]), p1 = unpack2(acc[i][1]);
            float2 p2 = unpack2(acc[i][2]), p3 = unpack2(acc[i][3]);
            *(float4*)(Pp + (size_t)m * 1024 + bn + tx * 4)      = make_float4(p0.x, p0.y, p1.x, p1.y);
            *(float4*)(Pp + (size_t)m * 1024 + bn + tx * 4 + 64) = make_float4(p2.x, p2.y, p3.x, p3.y);
        }
}

// ---------------- rpn GEMM, 256 threads, 8x8 micro, im2col fused ----------------
__device__ __forceinline__ float4 load_feat_quad(int k, int p)
{
    int ci = k / 9, r = k - ci * 9, dy = r / 3, dx = r - dy * 3;
    int py = p >> 5, px = p & 31;                      // px multiple of 4
    int y = py + dy - 1;
    int x0 = px + dx - 1;
    float4 v = make_float4(0.f, 0.f, 0.f, 0.f);
    if ((unsigned)y < 32u) {
        const float* frow = g_feat + ci * 1024 + y * 32 + x0;
        v.x = (x0 >= 0) ? frow[0] : 0.f;
        v.y = frow[1];
        v.z = frow[2];
        v.w = (x0 + 3 <= 31) ? frow[3] : 0.f;
    }
    return v;
}

__global__ void __launch_bounds__(256, 2)
gemm128rpn_k(const float* __restrict__ A, float* __restrict__ P, int ksplit)
{
    __shared__ float As[2][8][132];
    __shared__ float Bs[2][8][128];

    const int bn = blockIdx.x * 128;
    const int bm = blockIdx.y * 128;
    const int kbase = blockIdx.z * ksplit;
    const int tid = threadIdx.x;
    const int tx = tid & 15, ty = tid >> 4;
    const int alm = tid >> 1, alk = (tid & 1) * 4;
    const int blk = tid >> 5, bln = (tid & 31) * 4;

    const float* Aptr = A + (size_t)(bm + alm) * 4608 + kbase + alk;
    const int bp = bn + bln;

    u64 acc[8][4];
#pragma unroll
    for (int i = 0; i < 8; i++)
#pragma unroll
        for (int j = 0; j < 4; j++) acc[i][j] = 0ull;

    float4 av = *(const float4*)Aptr;
    float4 bv = load_feat_quad(kbase + blk, bp);

    As[0][alk + 0][alm] = av.x; As[0][alk + 1][alm] = av.y;
    As[0][alk + 2][alm] = av.z; As[0][alk + 3][alm] = av.w;
    *(float4*)&Bs[0][blk][bln] = bv;
    __syncthreads();

    int buf = 0;
    for (int k0 = 0; k0 < ksplit; k0 += 8) {
        bool more = (k0 + 8 < ksplit);
        if (more) {
            av = *(const float4*)(Aptr + k0 + 8);
            bv = load_feat_quad(kbase + k0 + 8 + blk, bp);
        }
#pragma unroll
        for (int kk = 0; kk < 8; kk++) {
            float4 a0 = *(const float4*)&As[buf][kk][ty * 4];
            float4 a1 = *(const float4*)&As[buf][kk][ty * 4 + 64];
            const u64* Bk = (const u64*)&Bs[buf][kk][0];
            u64 bb0 = Bk[tx * 2],      bb1 = Bk[tx * 2 + 1];
            u64 bb2 = Bk[tx * 2 + 32], bb3 = Bk[tx * 2 + 33];
            float a[8] = {a0.x, a0.y, a0.z, a0.w, a1.x, a1.y, a1.z, a1.w};
#pragma unroll
            for (int i = 0; i < 8; i++) {
                u64 ad = pack2(a[i], a[i]);
                ffma2(acc[i][0], ad, bb0);
                ffma2(acc[i][1], ad, bb1);
                ffma2(acc[i][2], ad, bb2);
                ffma2(acc[i][3], ad, bb3);
            }
        }
        if (more) {
            int nb = buf ^ 1;
            As[nb][alk + 0][alm] = av.x; As[nb][alk + 1][alm] = av.y;
            As[nb][alk + 2][alm] = av.z; As[nb][alk + 3][alm] = av.w;
            *(float4*)&Bs[nb][blk][bln] = bv;
        }
        __syncthreads();
        buf ^= 1;
    }

    float* Pp = P + (size_t)blockIdx.z * 512 * 1024;
#pragma unroll
    for (int ih = 0; ih < 2; ih++)
#pragma unroll
        for (int r2 = 0; r2 < 4; r2++) {
            int i = ih * 4 + r2;
            int m = bm + ih * 64 + ty * 4 + r2;
            float2 p0 = unpack2(acc[i][0]), p1 = unpack2(acc[i][1]);
            float2 p2 = unpack2(acc[i][2]), p3 = unpack2(acc[i][3]);
            *(float4*)(Pp + (size_t)m * 1024 + bn + tx * 4)      = make_float4(p0.x, p0.y, p1.x, p1.y);
            *(float4*)(Pp + (size_t)m * 1024 + bn + tx * 4 + 64) = make_float4(p2.x, p2.y, p3.x, p3.y);
        }
}

// ---------------- deterministic split-K reduce (+bias+relu) ----------------
__global__ void reduce_k(const float* __restrict__ P, float* __restrict__ C,
                         const float* __restrict__ bias, int S, int relu)
{
    int idx = blockIdx.x * blockDim.x + threadIdx.x;   // 131072 threads (float4)
    int m = idx >> 8, n4 = (idx & 255) * 4;
    float4 acc = make_float4(0.f, 0.f, 0.f, 0.f);
    for (int s = 0; s < S; s++) {                      // fixed order
        float4 v = *(const float4*)(P + ((size_t)s * 512 + m) * 1024 + n4);
        acc.x += v.x; acc.y += v.y; acc.z += v.z; acc.w += v.w;
    }
    float bb = bias[m];
    acc.x += bb; acc.y += bb; acc.z += bb; acc.w += bb;
    if (relu) {
        acc.x = fmaxf(acc.x, 0.f); acc.y = fmaxf(acc.y, 0.f);
        acc.z = fmaxf(acc.z, 0.f); acc.w = fmaxf(acc.w, 0.f);
    }
    *(float4*)(C + (size_t)m * 1024 + n4) = acc;
}

// ---------------- stage head weights into one contiguous matrix ----------------
__global__ void copy_wh_k(const float* __restrict__ wc, const float* __restrict__ bc,
                          const float* __restrict__ wb, const float* __restrict__ bb2)
{
    int i = blockIdx.x * blockDim.x + threadIdx.x;     // 23040 threads
    if (i < 9 * 512)       g_wh[i] = wc[9 * 512 + i];          // cls ch 9..17
    else if (i < 45 * 512) g_wh[i] = wb[i - 9 * 512];          // box ch 0..35
    if (i < 9)             g_bh[i] = bc[9 + i];
    else if (i < 45)       g_bh[i] = bb2[i - 9];
}

// ---------------- small GEMM for heads: C[45][1024] = wh x hid ----------------
__global__ void gemm_k(const float* __restrict__ A, const float* __restrict__ B,
                       float* __restrict__ C, int M, int K,
                       const float* __restrict__ bias)
{
    __shared__ float As[16][68];
    __shared__ float Bs[16][64];

    const int bn  = blockIdx.x * 64;
    const int tid = threadIdx.x;
    const int tx  = tid & 15, ty = tid >> 4;
    const int lm  = tid >> 2, lkq = (tid & 3) * 4;
    const int lkb = tid >> 4, ln4 = (tid & 15) * 4;

    float acc[4][4] = {};

    float4 av = make_float4(0.f, 0.f, 0.f, 0.f);
    if (lm < M) av = *(const float4*)(A + (size_t)lm * K + lkq);
    float4 bv = *(const float4*)(B + (size_t)lkb * 1024 + bn + ln4);

    for (int k0 = 0; k0 < K; k0 += 16) {
        As[lkq + 0][lm] = av.x; As[lkq + 1][lm] = av.y;
        As[lkq + 2][lm] = av.z; As[lkq + 3][lm] = av.w;
        *(float4*)&Bs[lkb][ln4] = bv;
        __syncthreads();

        int kn = k0 + 16;
        if (kn < K) {
            av = make_float4(0.f, 0.f, 0.f, 0.f);
            if (lm < M) av = *(const float4*)(A + (size_t)lm * K + kn + lkq);
            bv = *(const float4*)(B + (size_t)(kn + lkb) * 1024 + bn + ln4);
        }

#pragma unroll
        for (int k = 0; k < 16; k++) {
            float4 a = *(const float4*)&As[k][ty * 4];
            float4 b = *(const float4*)&Bs[k][tx * 4];
            acc[0][0] += a.x * b.x; acc[0][1] += a.x * b.y; acc[0][2] += a.x * b.z; acc[0][3] += a.x * b.w;
            acc[1][0] += a.y * b.x; acc[1][1] += a.y * b.y; acc[1][2] += a.y * b.z; acc[1][3] += a.y * b.w;
            acc[2][0] += a.z * b.x; acc[2][1] += a.z * b.y; acc[2][2] += a.z * b.z; acc[2][3] += a.z * b.w;
            acc[3][0] += a.w * b.x; acc[3][1] += a.w * b.y; acc[3][2] += a.w * b.z; acc[3][3] += a.w * b.w;
        }
        __syncthreads();
    }

#pragma unroll
    for (int r = 0; r < 4; r++) {
        int m = ty * 4 + r;
        if (m < M) {
            float bb = bias[m];
            float4 o = make_float4(acc[r][0] + bb, acc[r][1] + bb, acc[r][2] + bb, acc[r][3] + bb);
            *(float4*)(C + (size_t)m * 1024 + bn + tx * 4) = o;
        }
    }
}

// ---------------- fused decode + per-run bitonic sort (9 blocks x 512) ----------------
__global__ void decode_sort_k(const float* __restrict__ anchors)
{
    __shared__ u64 sk[1024];
    int base = blockIdx.x << 10, t = threadIdx.x;      // 512 threads

#pragma unroll
    for (int half = 0; half < 2; half++) {
        int e = t + half * 512;
        int i = base + e;
        int p = i / 9, k = i - p * 9;
        float s  = g_head[k * 1024 + p];
        float d0 = g_head[(9 + k * 4 + 0) * 1024 + p];
        float d1 = g_head[(9 + k * 4 + 1) * 1024 + p];
        float d2 = g_head[(9 + k * 4 + 2) * 1024 + p];
        float d3 = g_head[(9 + k * 4 + 3) * 1024 + p];

        const float* a = anchors + (size_t)i * 4;
        float ax1 = a[0], ay1 = a[1], ax2 = a[2], ay2 = a[3];
        float wa = ax2 - ax1, ha = ay2 - ay1;
        float cxa = ax1 + 0.5f * wa, cya = ay1 + 0.5f * ha;
        float dw = fminf(fmaxf(d2, -4.f), 4.f);
        float dh = fminf(fmaxf(d3, -4.f), 4.f);
        float cx = cxa + d0 * wa, cy = cya + d1 * ha;
        float w  = wa * expf(dw), h = ha * expf(dh);
        float x1 = fmaxf(cx - 0.5f * w, 0.f);
        float y1 = fmaxf(cy - 0.5f * h, 0.f);
        float x2 = fminf(cx + 0.5f * w, 511.f);
        float y2 = fminf(cy + 0.5f * h, 511.f);
        g_prop[i] = make_float4(x1, y1, x2, y2);

        unsigned b   = __float_as_uint(s);
        unsigned asc = (b & 0x80000000u) ? ~b : (b | 0x80000000u);
        unsigned dsc = ~asc;
        sk[e] = ((u64)dsc << 32) | (unsigned)i;
    }
    __syncthreads();

    for (int k = 2; k <= 1024; k <<= 1) {
        for (int j = k >> 1; j > 0; j >>= 1) {
            for (int e = t; e < 1024; e += 512) {
                int ixj = e ^ j;
                if (ixj > e) {
                    u64 x = sk[e], y = sk[ixj];
                    bool up = ((e & k) == 0);
                    if (up ? (x > y) : (x < y)) { sk[e] = y; sk[ixj] = x; }
                }
            }
            __syncthreads();
        }
    }
    g_keys[base + t]       = sk[t];
    g_keys[base + t + 512] = sk[t + 512];
}

// ---------------- 9-way rank-merge, fused gather (writes sorted boxes) ----------------
__global__ void merge9_k(const u64* __restrict__ src)
{
    int i = blockIdx.x * blockDim.x + threadIdx.x;     // 9216 threads
    u64 v = src[i];
    int rank = 0;
#pragma unroll
    for (int run = 0; run < 9; run++) {
        const u64* base = src + (run << 10);
        int pos = 0;
#pragma unroll
        for (int w = 512; w >= 1; w >>= 1)
            if (base[pos + w - 1] < v) pos += w;
        if (base[pos] < v) pos++;
        rank += pos;
    }
    g_boxes[rank] = g_prop[(int)(v & 0xFFFFFFFFull)];
}

// ---------------- NMS bitmask (upper triangle only; sub-diagonal blocks exit pre-load) ----------------
__global__ void nms_mask_k()                           // grid (144, 36), 256 threads
{
    __shared__ float4 cb[64];
    int bx = blockIdx.x;
    int by = blockIdx.y;
    if (bx < by * 4) return;                           // whole block below diagonal: uniform exit

    int t = threadIdx.x;
    int i = by * 256 + t;
    if (t < 64) cb[t] = g_boxes[bx * 64 + t];
    __syncthreads();

    if (bx < (i >> 6)) return;                         // per-row: word never read

    float4 b  = g_boxes[i];
    float  ai = (b.z - b.x) * (b.w - b.y);
    u64 m = 0ull;
#pragma unroll 4
    for (int jj = 0; jj < 64; jj++) {
        int j = bx * 64 + jj;
        if (j > i) {
            float4 c  = cb[jj];
            float  aj = (c.z - c.x) * (c.w - c.y);
            float iw = fmaxf(fminf(b.z, c.z) - fmaxf(b.x, c.x), 0.f);
            float ih = fmaxf(fminf(b.w, c.w) - fmaxf(b.y, c.y), 0.f);
            float inter = iw * ih;
            float iou = inter / (ai + aj - inter + 1e-9f);
            if (iou > IOU_THR) m |= (1ull << jj);
        }
    }
    g_mask[(size_t)i * NWORDS + bx] = m;
}

// ---------------- chunked greedy NMS reduce (exact serial semantics) ----------------
__global__ void nms_reduce_k(float* __restrict__ out)
{
    __shared__ u64 remv[NWORDS];
    __shared__ u64 keepw[NWORDS];
    __shared__ u64 diag[2][64];
    __shared__ int chunkj[64];
    __shared__ int sel[TOPK];
    __shared__ int s_cnt, s_ccnt, s_done;

    int t = threadIdx.x;                               // 192 threads
    if (t < NWORDS) { remv[t] = 0ull; keepw[t] = 0ull; }
    if (t == 0) { s_cnt = 0; s_done = 0; }
    if (t < 64) diag[0][t] = g_mask[(size_t)t * NWORDS + 0];
    __syncthreads();

    for (int c = 0; c < NWORDS; c++) {
        int buf = c & 1;
        if (t == 0) {
            u64 w  = remv[c];
            u64 kw = 0ull;
            int cc = 0;
            int cnt = s_cnt;
            for (int j = 0; j < 64; j++) {
                if (!((w >> j) & 1ull)) {
                    sel[cnt++] = c * 64 + j;
                    kw |= 1ull << j;
                    chunkj[cc++] = j;
                    if (cnt >= TOPK) break;
                    w |= diag[buf][j];
                }
            }
            keepw[c] = kw;
            s_cnt = cnt;
            s_ccnt = cc;
            if (cnt >= TOPK) s_done = 1;
        }
        __syncthreads();
        if (s_done) break;

        if (t >= 64 && t < 128 && c + 1 < NWORDS) {
            int tt = t - 64;
            diag[buf ^ 1][tt] =
                g_mask[(size_t)((c + 1) * 64 + tt) * NWORDS + (c + 1)];
        }

        if (t < NWORDS && t > c) {
            u64 r = remv[t];
            int cc = s_ccnt;
            for (int q = 0; q < cc; q++)
                r |= g_mask[(size_t)(c * 64 + chunkj[q]) * NWORDS + t];
            remv[t] = r;
        }
        __syncthreads();
    }
    __syncthreads();

    if (t == 0 && s_cnt < TOPK) {
        int cnt = s_cnt;
        for (int i = 0; i < NANCH && cnt < TOPK; i++)
            if (!((keepw[i >> 6] >> (i & 63)) & 1ull)) sel[cnt++] = i;
        s_cnt = cnt;
    }
    __syncthreads();

    for (int s = t; s < TOPK; s += blockDim.x) {
        float4 b = g_boxes[sel[s]];
        out[s * 4 + 0] = b.x; out[s * 4 + 1] = b.y;
        out[s * 4 + 2] = b.z; out[s * 4 + 3] = b.w;
    }
}

// ---------------- launch ----------------
extern "C" void kernel_launch(void* const* d_in, const int* in_sizes, int n_in,
                              void* d_out, int out_size)
{
    const float* img     = (const float*)d_in[0];
    const float* anchors = (const float*)d_in[1];
    const float* w_bb    = (const float*)d_in[2];
    const float* b_bb    = (const float*)d_in[3];
    const float* w_rpn   = (const float*)d_in[4];
    const float* b_rpn   = (const float*)d_in[5];
    const float* w_cls   = (const float*)d_in[6];
    const float* b_cls   = (const float*)d_in[7];
    const float* w_box   = (const float*)d_in[8];
    const float* b_box   = (const float*)d_in[9];
    float* out = (float*)d_out;

    float *feat, *hid, *head, *part, *wh, *bh;
    u64 *keys;
    cudaGetSymbolAddress((void**)&feat,  g_feat);
    cudaGetSymbolAddress((void**)&hid,   g_hid);
    cudaGetSymbolAddress((void**)&head,  g_head);
    cudaGetSymbolAddress((void**)&part,  g_part);
    cudaGetSymbolAddress((void**)&wh,    g_wh);
    cudaGetSymbolAddress((void**)&bh,    g_bh);
    cudaGetSymbolAddress((void**)&keys,  g_keys);

    copy_wh_k<<<90, 256>>>(w_cls, b_cls, w_box, b_box);            // #1 (independent)

    // backbone conv, im2col fused: split-K 8 (K=768, ksplit=96) -> 256 CTAs
    gemm128bb_k<<<dim3(8, 4, 8), 256>>>(w_bb, img, part, 96);      // #2
    reduce_k<<<512, 256>>>(part, feat, b_bb, 8, 1);                // #3

    // rpn conv, im2col fused: split-K 9 (K=4608, ksplit=512) -> 288 CTAs (1 wave, balanced)
    gemm128rpn_k<<<dim3(8, 4, 9), 256>>>(w_rpn, part, 512);        // #4 <- profiled
    reduce_k<<<512, 256>>>(part, hid, b_rpn, 9, 1);                // #5

    // heads: one 45-row GEMM
    gemm_k<<<16, 256>>>(wh, hid, head, 45, 512, bh);               // #6

    // decode + per-run sort (fused), then 9-way rank-merge writing sorted boxes
    decode_sort_k<<<9, 512>>>(anchors);                            // #7
    merge9_k<<<36, 256>>>(keys);                                   // #8

    // NMS
    nms_mask_k<<<dim3(NWORDS, 36), 256>>>();                       // #9
    nms_reduce_k<<<1, 192>>>(out);                                 // #10
}

// round 15
// speedup vs baseline: 1.1524x; 1.0565x over previous
#include <cuda_runtime.h>
#include <cstdint>

// ---------------- problem constants ----------------
#define NANCH   9216            // 1024*9
#define NWORDS  144             // 9216/64
#define IOU_THR 0.7f
#define TOPK    300

typedef unsigned long long u64;

// ---------------- scratch (static __device__, allocation-free) ----------------
__device__ float  g_feat[512 * 1024];          // backbone features      (2 MB)
__device__ float  g_hid [512 * 1024];          // rpn hidden             (2 MB)
__device__ float  g_part[9 * 512 * 1024];      // split-K partials      (19 MB)
__device__ float  g_head[45 * 1024];           // rows 0..8 cls ch9..17, 9..44 box
__device__ float  g_wh[45 * 512];              // staged head weights
__device__ float  g_bh[45];                    // staged head bias
__device__ float4 g_prop[NANCH];
__device__ u64    g_keys[NANCH];               // 9 sorted runs of 1024
__device__ float4 g_boxes[NANCH];
__device__ u64    g_mask[(size_t)NANCH * NWORDS]; // 10.6 MB

// ---------------- packed f32x2 helpers ----------------
__device__ __forceinline__ void ffma2(u64& d, u64 a, u64 b)
{
    asm("fma.rn.f32x2 %0, %1, %2, %0;" : "+l"(d) : "l"(a), "l"(b));
}
__device__ __forceinline__ u64 pack2(float lo, float hi)
{
    u64 r;
    asm("mov.b64 %0, {%1, %2};" : "=l"(r) : "f"(lo), "f"(hi));
    return r;
}
__device__ __forceinline__ float2 unpack2(u64 v)
{
    float2 r;
    asm("mov.b64 {%0, %1}, %2;" : "=f"(r.x), "=f"(r.y) : "l"(v));
    return r;
}

// ---------------- backbone GEMM, 256 threads, 8x8 micro, im2col fused ----------------
__global__ void __launch_bounds__(256, 2)
gemm128bb_k(const float* __restrict__ A, const float* __restrict__ img,
            float* __restrict__ P, int ksplit)
{
    __shared__ float As[2][8][132];
    __shared__ float Bs[2][8][128];

    const int bn = blockIdx.x * 128;
    const int bm = blockIdx.y * 128;
    const int kbase = blockIdx.z * ksplit;
    const int tid = threadIdx.x;
    const int tx = tid & 15, ty = tid >> 4;
    const int alm = tid >> 1, alk = (tid & 1) * 4;     // A loader
    const int bkq = (tid & 1) * 4;                     // B loader: k quad (k-fast)
    const int bpp = tid >> 1;                          // B loader: column

    const float* Aptr = A + (size_t)(bm + alm) * 768 + kbase + alk;
    const int p = bn + bpp, py = p >> 5, px = p & 31;

    u64 acc[8][4];
#pragma unroll
    for (int i = 0; i < 8; i++)
#pragma unroll
        for (int j = 0; j < 4; j++) acc[i][j] = 0ull;

    float4 av = *(const float4*)Aptr;
    int k = kbase + bkq;
    int ci = k >> 8, r = k & 255, ky = r >> 4, kx = r & 15;
    float4 bv = *(const float4*)(img + ci * 262144 + (py * 16 + ky) * 512 + px * 16 + kx);

    As[0][alk + 0][alm] = av.x; As[0][alk + 1][alm] = av.y;
    As[0][alk + 2][alm] = av.z; As[0][alk + 3][alm] = av.w;
    Bs[0][bkq + 0][bpp] = bv.x; Bs[0][bkq + 1][bpp] = bv.y;
    Bs[0][bkq + 2][bpp] = bv.z; Bs[0][bkq + 3][bpp] = bv.w;
    __syncthreads();

    int buf = 0;
    for (int k0 = 0; k0 < ksplit; k0 += 8) {
        bool more = (k0 + 8 < ksplit);
        if (more) {
            av = *(const float4*)(Aptr + k0 + 8);
            k = kbase + k0 + 8 + bkq;
            ci = k >> 8; r = k & 255; ky = r >> 4; kx = r & 15;
            bv = *(const float4*)(img + ci * 262144 + (py * 16 + ky) * 512 + px * 16 + kx);
        }
#pragma unroll
        for (int kk = 0; kk < 8; kk++) {
            float4 a0 = *(const float4*)&As[buf][kk][ty * 4];
            float4 a1 = *(const float4*)&As[buf][kk][ty * 4 + 64];
            const ulonglong2* Bk = (const ulonglong2*)&Bs[buf][kk][0];
            ulonglong2 B01 = Bk[tx];                   // LDS.128: bb0,bb1
            ulonglong2 B23 = Bk[tx + 16];              // LDS.128: bb2,bb3
            float a[8] = {a0.x, a0.y, a0.z, a0.w, a1.x, a1.y, a1.z, a1.w};
#pragma unroll
            for (int i = 0; i < 8; i++) {
                u64 ad = pack2(a[i], a[i]);
                ffma2(acc[i][0], ad, B01.x);
                ffma2(acc[i][1], ad, B01.y);
                ffma2(acc[i][2], ad, B23.x);
                ffma2(acc[i][3], ad, B23.y);
            }
        }
        if (more) {
            int nb = buf ^ 1;
            As[nb][alk + 0][alm] = av.x; As[nb][alk + 1][alm] = av.y;
            As[nb][alk + 2][alm] = av.z; As[nb][alk + 3][alm] = av.w;
            Bs[nb][bkq + 0][bpp] = bv.x; Bs[nb][bkq + 1][bpp] = bv.y;
            Bs[nb][bkq + 2][bpp] = bv.z; Bs[nb][bkq + 3][bpp] = bv.w;
        }
        __syncthreads();
        buf ^= 1;
    }

    float* Pp = P + (size_t)blockIdx.z * 512 * 1024;
#pragma unroll
    for (int ih = 0; ih < 2; ih++)
#pragma unroll
        for (int r2 = 0; r2 < 4; r2++) {
            int i = ih * 4 + r2;
            int m = bm + ih * 64 + ty * 4 + r2;
            float2 p0 = unpack2(acc[i][0]), p1 = unpack2(acc[i][1]);
            float2 p2 = unpack2(acc[i][2]), p3 = unpack2(acc[i][3]);
            *(float4*)(Pp + (size_t)m * 1024 + bn + tx * 4)      = make_float4(p0.x, p0.y, p1.x, p1.y);
            *(float4*)(Pp + (size_t)m * 1024 + bn + tx * 4 + 64) = make_float4(p2.x, p2.y, p3.x, p3.y);
        }
}

// ---------------- rpn GEMM, 256 threads, 8x8 micro, im2col fused ----------------
__device__ __forceinline__ float4 load_feat_quad(int k, int p)
{
    int ci = k / 9, r = k - ci * 9, dy = r / 3, dx = r - dy * 3;
    int py = p >> 5, px = p & 31;                      // px multiple of 4
    int y = py + dy - 1;
    int x0 = px + dx - 1;
    float4 v = make_float4(0.f, 0.f, 0.f, 0.f);
    if ((unsigned)y < 32u) {
        const float* frow = g_feat + ci * 1024 + y * 32 + x0;
        v.x = (x0 >= 0) ? frow[0] : 0.f;
        v.y = frow[1];
        v.z = frow[2];
        v.w = (x0 + 3 <= 31) ? frow[3] : 0.f;
    }
    return v;
}

__global__ void __launch_bounds__(256, 2)
gemm128rpn_k(const float* __restrict__ A, float* __restrict__ P, int ksplit)
{
    __shared__ float As[2][8][132];
    __shared__ float Bs[2][8][128];

    const int bn = blockIdx.x * 128;
    const int bm = blockIdx.y * 128;
    const int kbase = blockIdx.z * ksplit;
    const int tid = threadIdx.x;
    const int tx = tid & 15, ty = tid >> 4;
    const int alm = tid >> 1, alk = (tid & 1) * 4;
    const int blk = tid >> 5, bln = (tid & 31) * 4;

    const float* Aptr = A + (size_t)(bm + alm) * 4608 + kbase + alk;
    const int bp = bn + bln;

    u64 acc[8][4];
#pragma unroll
    for (int i = 0; i < 8; i++)
#pragma unroll
        for (int j = 0; j < 4; j++) acc[i][j] = 0ull;

    float4 av = *(const float4*)Aptr;
    float4 bv = load_feat_quad(kbase + blk, bp);

    As[0][alk + 0][alm] = av.x; As[0][alk + 1][alm] = av.y;
    As[0][alk + 2][alm] = av.z; As[0][alk + 3][alm] = av.w;
    *(float4*)&Bs[0][blk][bln] = bv;
    __syncthreads();

    int buf = 0;
    for (int k0 = 0; k0 < ksplit; k0 += 8) {
        bool more = (k0 + 8 < ksplit);
        if (more) {
            av = *(const float4*)(Aptr + k0 + 8);
            bv = load_feat_quad(kbase + k0 + 8 + blk, bp);
        }
#pragma unroll
        for (int kk = 0; kk < 8; kk++) {
            float4 a0 = *(const float4*)&As[buf][kk][ty * 4];
            float4 a1 = *(const float4*)&As[buf][kk][ty * 4 + 64];
            const ulonglong2* Bk = (const ulonglong2*)&Bs[buf][kk][0];
            ulonglong2 B01 = Bk[tx];                   // LDS.128: bb0,bb1
            ulonglong2 B23 = Bk[tx + 16];              // LDS.128: bb2,bb3
            float a[8] = {a0.x, a0.y, a0.z, a0.w, a1.x, a1.y, a1.z, a1.w};
#pragma unroll
            for (int i = 0; i < 8; i++) {
                u64 ad = pack2(a[i], a[i]);
                ffma2(acc[i][0], ad, B01.x);
                ffma2(acc[i][1], ad, B01.y);
                ffma2(acc[i][2], ad, B23.x);
                ffma2(acc[i][3], ad, B23.y);
            }
        }
        if (more) {
            int nb = buf ^ 1;
            As[nb][alk + 0][alm] = av.x; As[nb][alk + 1][alm] = av.y;
            As[nb][alk + 2][alm] = av.z; As[nb][alk + 3][alm] = av.w;
            *(float4*)&Bs[nb][blk][bln] = bv;
        }
        __syncthreads();
        buf ^= 1;
    }

    float* Pp = P + (size_t)blockIdx.z * 512 * 1024;
#pragma unroll
    for (int ih = 0; ih < 2; ih++)
#pragma unroll
        for (int r2 = 0; r2 < 4; r2++) {
            int i = ih * 4 + r2;
            int m = bm + ih * 64 + ty * 4 + r2;
            float2 p0 = unpack2(acc[i][0]), p1 = unpack2(acc[i][1]);
            float2 p2 = unpack2(acc[i][2]), p3 = unpack2(acc[i][3]);
            *(float4*)(Pp + (size_t)m * 1024 + bn + tx * 4)      = make_float4(p0.x, p0.y, p1.x, p1.y);
            *(float4*)(Pp + (size_t)m * 1024 + bn + tx * 4 + 64) = make_float4(p2.x, p2.y, p3.x, p3.y);
        }
}

// ---------------- deterministic split-K reduce (+bias+relu) ----------------
__global__ void reduce_k(const float* __restrict__ P, float* __restrict__ C,
                         const float* __restrict__ bias, int S, int relu)
{
    int idx = blockIdx.x * blockDim.x + threadIdx.x;   // 131072 threads (float4)
    int m = idx >> 8, n4 = (idx & 255) * 4;
    float4 acc = make_float4(0.f, 0.f, 0.f, 0.f);
    for (int s = 0; s < S; s++) {                      // fixed order
        float4 v = *(const float4*)(P + ((size_t)s * 512 + m) * 1024 + n4);
        acc.x += v.x; acc.y += v.y; acc.z += v.z; acc.w += v.w;
    }
    float bb = bias[m];
    acc.x += bb; acc.y += bb; acc.z += bb; acc.w += bb;
    if (relu) {
        acc.x = fmaxf(acc.x, 0.f); acc.y = fmaxf(acc.y, 0.f);
        acc.z = fmaxf(acc.z, 0.f); acc.w = fmaxf(acc.w, 0.f);
    }
    *(float4*)(C + (size_t)m * 1024 + n4) = acc;
}

// ---------------- stage head weights into one contiguous matrix ----------------
__global__ void copy_wh_k(const float* __restrict__ wc, const float* __restrict__ bc,
                          const float* __restrict__ wb, const float* __restrict__ bb2)
{
    int i = blockIdx.x * blockDim.x + threadIdx.x;     // 23040 threads
    if (i < 9 * 512)       g_wh[i] = wc[9 * 512 + i];          // cls ch 9..17
    else if (i < 45 * 512) g_wh[i] = wb[i - 9 * 512];          // box ch 0..35
    if (i < 9)             g_bh[i] = bc[9 + i];
    else if (i < 45)       g_bh[i] = bb2[i - 9];
}

// ---------------- heads GEMM split-K: P45[s][45][1024] = wh[:, ks] x hid[ks, :] ----------------
__global__ void gemm45_k(const float* __restrict__ A, const float* __restrict__ B,
                         float* __restrict__ P, int ksplit)
{
    __shared__ float As[16][68];
    __shared__ float Bs[16][64];

    const int bn  = blockIdx.x * 64;
    const int kbase = blockIdx.z * ksplit;
    const int tid = threadIdx.x;
    const int tx  = tid & 15, ty = tid >> 4;
    const int lm  = tid >> 2, lkq = (tid & 3) * 4;
    const int lkb = tid >> 4, ln4 = (tid & 15) * 4;

    float acc[4][4] = {};

    float4 av = make_float4(0.f, 0.f, 0.f, 0.f);
    if (lm < 45) av = *(const float4*)(A + (size_t)lm * 512 + kbase + lkq);
    float4 bv = *(const float4*)(B + (size_t)(kbase + lkb) * 1024 + bn + ln4);

    for (int k0 = 0; k0 < ksplit; k0 += 16) {
        As[lkq + 0][lm] = av.x; As[lkq + 1][lm] = av.y;
        As[lkq + 2][lm] = av.z; As[lkq + 3][lm] = av.w;
        *(float4*)&Bs[lkb][ln4] = bv;
        __syncthreads();

        int kn = k0 + 16;
        if (kn < ksplit) {
            av = make_float4(0.f, 0.f, 0.f, 0.f);
            if (lm < 45) av = *(const float4*)(A + (size_t)lm * 512 + kbase + kn + lkq);
            bv = *(const float4*)(B + (size_t)(kbase + kn + lkb) * 1024 + bn + ln4);
        }

#pragma unroll
        for (int k = 0; k < 16; k++) {
            float4 a = *(const float4*)&As[k][ty * 4];
            float4 b = *(const float4*)&Bs[k][tx * 4];
            acc[0][0] += a.x * b.x; acc[0][1] += a.x * b.y; acc[0][2] += a.x * b.z; acc[0][3] += a.x * b.w;
            acc[1][0] += a.y * b.x; acc[1][1] += a.y * b.y; acc[1][2] += a.y * b.z; acc[1][3] += a.y * b.w;
            acc[2][0] += a.z * b.x; acc[2][1] += a.z * b.y; acc[2][2] += a.z * b.z; acc[2][3] += a.z * b.w;
            acc[3][0] += a.w * b.x; acc[3][1] += a.w * b.y; acc[3][2] += a.w * b.z; acc[3][3] += a.w * b.w;
        }
        __syncthreads();
    }

    float* Pp = P + (size_t)blockIdx.z * 45 * 1024;
#pragma unroll
    for (int r = 0; r < 4; r++) {
        int m = ty * 4 + r;
        if (m < 45)
            *(float4*)(Pp + (size_t)m * 1024 + bn + tx * 4)
                = make_float4(acc[r][0], acc[r][1], acc[r][2], acc[r][3]);
    }
}

// ---------------- deterministic heads reduce (+bias) ----------------
__global__ void reduce45_k(const float* __restrict__ P)
{
    int idx = blockIdx.x * blockDim.x + threadIdx.x;   // 45*256 threads (float4)
    int m = idx >> 8, n4 = (idx & 255) * 4;
    float4 acc = make_float4(0.f, 0.f, 0.f, 0.f);
#pragma unroll
    for (int s = 0; s < 4; s++) {                      // fixed order
        float4 v = *(const float4*)(P + ((size_t)s * 45 + m) * 1024 + n4);
        acc.x += v.x; acc.y += v.y; acc.z += v.z; acc.w += v.w;
    }
    float bb = g_bh[m];
    acc.x += bb; acc.y += bb; acc.z += bb; acc.w += bb;
    *(float4*)(g_head + (size_t)m * 1024 + n4) = acc;
}

// ---------------- fused decode + per-run bitonic sort (9 blocks x 512) ----------------
__global__ void decode_sort_k(const float* __restrict__ anchors)
{
    __shared__ u64 sk[1024];
    int base = blockIdx.x << 10, t = threadIdx.x;      // 512 threads

#pragma unroll
    for (int half = 0; half < 2; half++) {
        int e = t + half * 512;
        int i = base + e;
        int p = i / 9, k = i - p * 9;
        float s  = g_head[k * 1024 + p];
        float d0 = g_head[(9 + k * 4 + 0) * 1024 + p];
        float d1 = g_head[(9 + k * 4 + 1) * 1024 + p];
        float d2 = g_head[(9 + k * 4 + 2) * 1024 + p];
        float d3 = g_head[(9 + k * 4 + 3) * 1024 + p];

        const float* a = anchors + (size_t)i * 4;
        float ax1 = a[0], ay1 = a[1], ax2 = a[2], ay2 = a[3];
        float wa = ax2 - ax1, ha = ay2 - ay1;
        float cxa = ax1 + 0.5f * wa, cya = ay1 + 0.5f * ha;
        float dw = fminf(fmaxf(d2, -4.f), 4.f);
        float dh = fminf(fmaxf(d3, -4.f), 4.f);
        float cx = cxa + d0 * wa, cy = cya + d1 * ha;
        float w  = wa * expf(dw), h = ha * expf(dh);
        float x1 = fmaxf(cx - 0.5f * w, 0.f);
        float y1 = fmaxf(cy - 0.5f * h, 0.f);
        float x2 = fminf(cx + 0.5f * w, 511.f);
        float y2 = fminf(cy + 0.5f * h, 511.f);
        g_prop[i] = make_float4(x1, y1, x2, y2);

        unsigned b   = __float_as_uint(s);
        unsigned asc = (b & 0x80000000u) ? ~b : (b | 0x80000000u);
        unsigned dsc = ~asc;
        sk[e] = ((u64)dsc << 32) | (unsigned)i;
    }
    __syncthreads();

    for (int k = 2; k <= 1024; k <<= 1) {
        for (int j = k >> 1; j > 0; j >>= 1) {
            for (int e = t; e < 1024; e += 512) {
                int ixj = e ^ j;
                if (ixj > e) {
                    u64 x = sk[e], y = sk[ixj];
                    bool up = ((e & k) == 0);
                    if (up ? (x > y) : (x < y)) { sk[e] = y; sk[ixj] = x; }
                }
            }
            __syncthreads();
        }
    }
    g_keys[base + t]       = sk[t];
    g_keys[base + t + 512] = sk[t + 512];
}

// ---------------- 9-way rank-merge, fused gather (writes sorted boxes) ----------------
__global__ void merge9_k(const u64* __restrict__ src)
{
    int i = blockIdx.x * blockDim.x + threadIdx.x;     // 9216 threads
    u64 v = src[i];
    int rank = 0;
#pragma unroll
    for (int run = 0; run < 9; run++) {
        const u64* base = src + (run << 10);
        int pos = 0;
#pragma unroll
        for (int w = 512; w >= 1; w >>= 1)
            if (base[pos + w - 1] < v) pos += w;
        if (base[pos] < v) pos++;
        rank += pos;
    }
    g_boxes[rank] = g_prop[(int)(v & 0xFFFFFFFFull)];
}

// ---------------- NMS bitmask (upper triangle only; sub-diagonal blocks exit pre-load) ----------------
__global__ void nms_mask_k()                           // grid (144, 36), 256 threads
{
    __shared__ float4 cb[64];
    int bx = blockIdx.x;
    int by = blockIdx.y;
    if (bx < by * 4) return;                           // whole block below diagonal: uniform exit

    int t = threadIdx.x;
    int i = by * 256 + t;
    if (t < 64) cb[t] = g_boxes[bx * 64 + t];
    __syncthreads();

    if (bx < (i >> 6)) return;                         // per-row: word never read

    float4 b  = g_boxes[i];
    float  ai = (b.z - b.x) * (b.w - b.y);
    u64 m = 0ull;
#pragma unroll 4
    for (int jj = 0; jj < 64; jj++) {
        int j = bx * 64 + jj;
        if (j > i) {
            float4 c  = cb[jj];
            float  aj = (c.z - c.x) * (c.w - c.y);
            float iw = fmaxf(fminf(b.z, c.z) - fmaxf(b.x, c.x), 0.f);
            float ih = fmaxf(fminf(b.w, c.w) - fmaxf(b.y, c.y), 0.f);
            float inter = iw * ih;
            float iou = inter / (ai + aj - inter + 1e-9f);
            if (iou > IOU_THR) m |= (1ull << jj);
        }
    }
    g_mask[(size_t)i * NWORDS + bx] = m;
}

// ---------------- chunked greedy NMS reduce (exact serial semantics) ----------------
__global__ void nms_reduce_k(float* __restrict__ out)
{
    __shared__ u64 remv[NWORDS];
    __shared__ u64 keepw[NWORDS];
    __shared__ u64 diag[2][64];
    __shared__ int chunkj[64];
    __shared__ int sel[TOPK];
    __shared__ int s_cnt, s_ccnt, s_done;

    int t = threadIdx.x;                               // 192 threads
    if (t < NWORDS) { remv[t] = 0ull; keepw[t] = 0ull; }
    if (t == 0) { s_cnt = 0; s_done = 0; }
    if (t < 64) diag[0][t] = g_mask[(size_t)t * NWORDS + 0];
    __syncthreads();

    for (int c = 0; c < NWORDS; c++) {
        int buf = c & 1;
        if (t == 0) {
            u64 w  = remv[c];
            u64 kw = 0ull;
            int cc = 0;
            int cnt = s_cnt;
            for (int j = 0; j < 64; j++) {
                if (!((w >> j) & 1ull)) {
                    sel[cnt++] = c * 64 + j;
                    kw |= 1ull << j;
                    chunkj[cc++] = j;
                    if (cnt >= TOPK) break;
                    w |= diag[buf][j];
                }
            }
            keepw[c] = kw;
            s_cnt = cnt;
            s_ccnt = cc;
            if (cnt >= TOPK) s_done = 1;
        }
        __syncthreads();
        if (s_done) break;

        if (t >= 64 && t < 128 && c + 1 < NWORDS) {
            int tt = t - 64;
            diag[buf ^ 1][tt] =
                g_mask[(size_t)((c + 1) * 64 + tt) * NWORDS + (c + 1)];
        }

        if (t < NWORDS && t > c) {
            u64 r = remv[t];
            int cc = s_ccnt;
            for (int q = 0; q < cc; q++)
                r |= g_mask[(size_t)(c * 64 + chunkj[q]) * NWORDS + t];
            remv[t] = r;
        }
        __syncthreads();
    }
    __syncthreads();

    if (t == 0 && s_cnt < TOPK) {
        int cnt = s_cnt;
        for (int i = 0; i < NANCH && cnt < TOPK; i++)
            if (!((keepw[i >> 6] >> (i & 63)) & 1ull)) sel[cnt++] = i;
        s_cnt = cnt;
    }
    __syncthreads();

    for (int s = t; s < TOPK; s += blockDim.x) {
        float4 b = g_boxes[sel[s]];
        out[s * 4 + 0] = b.x; out[s * 4 + 1] = b.y;
        out[s * 4 + 2] = b.z; out[s * 4 + 3] = b.w;
    }
}

// ---------------- launch ----------------
extern "C" void kernel_launch(void* const* d_in, const int* in_sizes, int n_in,
                              void* d_out, int out_size)
{
    const float* img     = (const float*)d_in[0];
    const float* anchors = (const float*)d_in[1];
    const float* w_bb    = (const float*)d_in[2];
    const float* b_bb    = (const float*)d_in[3];
    const float* w_rpn   = (const float*)d_in[4];
    const float* b_rpn   = (const float*)d_in[5];
    const float* w_cls   = (const float*)d_in[6];
    const float* b_cls   = (const float*)d_in[7];
    const float* w_box   = (const float*)d_in[8];
    const float* b_box   = (const float*)d_in[9];
    float* out = (float*)d_out;

    float *feat, *hid, *part, *wh;
    u64 *keys;
    cudaGetSymbolAddress((void**)&feat,  g_feat);
    cudaGetSymbolAddress((void**)&hid,   g_hid);
    cudaGetSymbolAddress((void**)&part,  g_part);
    cudaGetSymbolAddress((void**)&wh,    g_wh);
    cudaGetSymbolAddress((void**)&keys,  g_keys);

    copy_wh_k<<<90, 256>>>(w_cls, b_cls, w_box, b_box);            // #1 (independent)

    // backbone conv, im2col fused: split-K 8 (K=768, ksplit=96) -> 256 CTAs
    gemm128bb_k<<<dim3(8, 4, 8), 256>>>(w_bb, img, part, 96);      // #2
    reduce_k<<<512, 256>>>(part, feat, b_bb, 8, 1);                // #3

    // rpn conv, im2col fused: split-K 9 (K=4608, ksplit=512) -> 288 CTAs (1 wave)
    gemm128rpn_k<<<dim3(8, 4, 9), 256>>>(w_rpn, part, 512);        // #4 <- profiled
    reduce_k<<<512, 256>>>(part, hid, b_rpn, 9, 1);                // #5

    // heads: split-K 4 (64 CTAs) + deterministic reduce
    gemm45_k<<<dim3(16, 1, 4), 256>>>(wh, hid, part, 128);         // #6
    reduce45_k<<<45, 256>>>(part);                                 // #7

    // decode + per-run sort (fused), then 9-way rank-merge writing sorted boxes
    decode_sort_k<<<9, 512>>>(anchors);                            // #8
    merge9_k<<<36, 256>>>(keys);                                   // #9

    // NMS
    nms_mask_k<<<dim3(NWORDS, 36), 256>>>();                       // #10
    nms_reduce_k<<<1, 192>>>(out);                                 // #11
}